// round 12
// baseline (speedup 1.0000x reference)
#include <cuda_runtime.h>
#include <cuda_fp16.h>
#include <math.h>
#include <stdint.h>

#define NCB   8
#define MEMB  1024
#define DEMB  128
#define HLAT  64
#define BATCH 256
#define LPER  (BATCH*HLAT)              /* 16384 per codebook */
#define ZQ_ELEMS (BATCH*NCB*DEMB*HLAT)  /* 16777216 */
#define IDX_ELEMS (BATCH*NCB*HLAT)      /* 131072 */

// ---------------- device scratch ----------------
__device__ int   g_indices[NCB*LPER];
__device__ float g_esq[NCB*MEMB];
__device__ int   g_esqmaxb[NCB];          // max esq per codebook (float bits, >0)
__device__ float g_xsq[NCB*LPER];
__device__ float g_part[2048];
__device__ float g_ent[NCB];
__device__ int   g_paircnt;
__device__ int   g_rescnt;
__device__ int2  g_pairlist[NCB*LPER];    // (.x = (n<<14)|l, .y = bidx | sidx<<16)
__device__ int   g_reslist[NCB*LPER];     // (n<<14)|l
// pre-swizzled fp16 embedding tiles (e*256): [n][mchunk 8][row 128][k 128]
__device__ __half g_bh[NCB*MEMB*DEMB];

// ---------------- PTX helpers ----------------
__device__ __forceinline__ uint32_t smem_u32(const void* p) {
    uint32_t a;
    asm("{ .reg .u64 t; cvta.to.shared.u64 t, %1; cvt.u32.u64 %0, t; }" : "=r"(a) : "l"(p));
    return a;
}
__device__ __forceinline__ void ldsm4(uint32_t* r, uint32_t addr) {
    asm volatile("ldmatrix.sync.aligned.m8n8.x4.shared.b16 {%0,%1,%2,%3}, [%4];"
        : "=r"(r[0]), "=r"(r[1]), "=r"(r[2]), "=r"(r[3]) : "r"(addr));
}
__device__ __forceinline__ void mma_f16(float* c, const uint32_t* a, const uint32_t* b) {
    asm volatile("mma.sync.aligned.m16n8k16.row.col.f32.f16.f16.f32 "
        "{%0,%1,%2,%3}, {%4,%5,%6,%7}, {%8,%9}, {%0,%1,%2,%3};"
        : "+f"(c[0]), "+f"(c[1]), "+f"(c[2]), "+f"(c[3])
        : "r"(a[0]), "r"(a[1]), "r"(a[2]), "r"(a[3]), "r"(b[0]), "r"(b[1]));
}
__device__ __forceinline__ void cp16(uint32_t dst, const void* src) {
    asm volatile("cp.async.cg.shared.global [%0], [%1], 16;" :: "r"(dst), "l"(src) : "memory");
}
#define CP_COMMIT() asm volatile("cp.async.commit_group;" ::: "memory")
#define CP_WAIT(n)  asm volatile("cp.async.wait_group %0;" :: "n"(n) : "memory")

// merge two sorted top-3 triples (values asc; indices for first two).
// Lexicographic (value, index) order for positions 1-2; value-only for third.
__device__ __forceinline__ void mrg3(float& a1, float& a2, float& a3, int& i1, int& i2,
                                     float b1, float b2, float b3, int j1, int j2) {
    if (b1 < a1 || (b1 == a1 && j1 < i1)) {
        float v; int t;
        v = a1; a1 = b1; b1 = v;  t = i1; i1 = j1; j1 = t;
        v = a2; a2 = b2; b2 = v;  t = i2; i2 = j2; j2 = t;
        v = a3; a3 = b3; b3 = v;
    }
    if (b1 < a2 || (b1 == a2 && j1 < i2)) {
        a3 = fminf(a2, b2);
        a2 = b1; i2 = j1;
    } else {
        a3 = fminf(a3, b1);
    }
}

// ---------------- e_sq (exact sequential) + per-n max + counter reset ----------------
__global__ void esq_kernel(const float* __restrict__ emb) {
    int t = blockIdx.x * blockDim.x + threadIdx.x;
    if (t == 0) { g_paircnt = 0; g_rescnt = 0; }
    if (t >= NCB*MEMB) return;
    const float* row = emb + (size_t)t * DEMB;
    float acc = 0.f;
    #pragma unroll 8
    for (int d = 0; d < DEMB; d++) {
        float v = row[d];
        acc = __fadd_rn(acc, __fmul_rn(v, v));
    }
    g_esq[t] = acc;
    atomicMax(&g_esqmaxb[t >> 10], __float_as_int(acc));   // acc > 0
}

// ---------------- x_sq (exact sequential) ----------------
__global__ void __launch_bounds__(256)
xsq_kernel(const float* __restrict__ x) {
    __shared__ float tile[8192];
    const int n = blockIdx.x & 7, b = blockIdx.x >> 3, tid = threadIdx.x;
    const size_t base = (size_t)b*65536 + (size_t)n*8192;
    for (int i = tid; i < 8192; i += 256) tile[i] = x[base + i];
    __syncthreads();
    if (tid < 64) {
        float acc = 0.f;
        #pragma unroll 8
        for (int d = 0; d < DEMB; d++) {
            float v = tile[d*64 + tid];
            acc = __fadd_rn(acc, __fmul_rn(v, v));
        }
        g_xsq[n*LPER + b*HLAT + tid] = acc;
    }
}

// ---------------- embedding -> swizzled fp16 (e*256) tiles, 128-code chunks ----------------
__global__ void bprep_kernel(const float* __restrict__ emb) {
    int u = blockIdx.x * blockDim.x + threadIdx.x;
    if (u >= NCB*MEMB*DEMB) return;
    float v = emb[u] * 256.0f;               // exact scale
    int d = u & 127, m = (u >> 7) & 1023, n = u >> 17;
    int row = m & 127, mc = m >> 7;
    int elem = ((n*8 + mc)*128 + row)*128 + (((d >> 3) ^ (row & 7)) << 3) + (d & 7);
    g_bh[elem] = __float2half_rn(v);
}

// ---------------- pass 1: fp16 1-MMA approximate argmin with top-3 ----------------
// CTA = (n, batch row). 8 warps = 2(l) x 4(m); warp tile 32x32.
// m-chunks of 128 codes (8 iters), B double-buffered 2x32KB -> 2 CTAs/SM.
// acc = x_f16 . (256*e)_f16 ; t = esq - acc/128.
__global__ void __launch_bounds__(256, 2)
argmin_mma(const float* __restrict__ x) {
    extern __shared__ char smraw[];
    uint32_t sraw = smem_u32(smraw);
    uint32_t sb = (sraw + 1023u) & ~1023u;
    char* sm = smraw + (sb - sraw);
    __half* Ahi = (__half*)(sm);              // 16KB @0
    // B buffers: buf0 @16384 (32KB), buf1 @49152 (32KB)
    float* esq_s = (float*)(sm + 81920);      // 4KB
    float* sb1 = (float*)(sm + 86016);        // 256 f32
    float* sb2 = (float*)(sm + 87040);        // 256 f32
    float* sb3 = (float*)(sm + 88064);        // 256 f32
    int*   si1 = (int*)  (sm + 89088);        // 256 int
    int*   si2 = (int*)  (sm + 90112);        // 256 int

    const int n  = blockIdx.x >> 8;
    const int lt = blockIdx.x & 255;          // batch row b
    const int l0 = lt * 64;
    const int tid  = threadIdx.x;
    const int lane = tid & 31;
    const int w    = tid >> 5;
    const int wl   = w & 1;     // l half (32 rows)
    const int wm   = w >> 1;    // m quarter (32 cols of the 128-chunk)

    // ---- prefetch B chunk 0 into buf0 ----
    {
        const char* src = (const char*)(g_bh + ((size_t)(n*8 + 0) << 14));
        uint32_t dst = sb + 16384;
        #pragma unroll
        for (int i = 0; i < 8; i++)
            cp16(dst + (tid + i*256)*16, src + (tid + i*256)*16);
        CP_COMMIT();
    }

    // stage e_sq
    for (int i = tid; i < 1024; i += 256) esq_s[i] = g_esq[n*1024 + i];

    // stage A tile in fp16 (swizzled): rows j = h (0..63), cols d
    for (int idx = tid; idx < 8192; idx += 256) {
        int d = idx >> 6, j = idx & 63;
        float v = x[(size_t)lt*65536 + (size_t)n*8192 + d*64 + j];
        int elem = j*128 + (((d >> 3) ^ (j & 7)) << 3) + (d & 7);
        Ahi[elem] = __float2half_rn(v);
    }

    // ldmatrix per-lane address precompute
    const uint32_t sAh = sb, sBh0 = sb + 16384;
    const int q  = lane >> 3;
    const int r8 = lane & 7;
    const int cqA = q >> 1;
    const int cqB = q & 1;
    uint32_t aBase[2]; int a7[2];
    #pragma unroll
    for (int t2 = 0; t2 < 2; t2++) {
        int rowA = wl*32 + t2*16 + r8 + (q & 1)*8;
        aBase[t2] = sAh + rowA*256; a7[t2] = rowA & 7;
    }
    uint32_t bBase[2]; int b7[2];
    #pragma unroll
    for (int p = 0; p < 2; p++) {
        int rowB = wm*32 + p*16 + r8 + (q >> 1)*8;
        bBase[p] = sBh0 + rowB*256; b7[p] = rowB & 7;
    }

    // top-3 per slot: slots = (t2, row-half)
    float best[4], sec[4], thr[4];
    int   bidx[4], sidx[4];
    #pragma unroll
    for (int s = 0; s < 4; s++) {
        best[s] = 3.4e38f; sec[s] = 3.4e38f; thr[s] = 3.4e38f;
        bidx[s] = 0; sidx[s] = 0;
    }

    const int col2 = (lane & 3) * 2;

#define INS(v, m, s) \
    if ((v) < thr[s]) { \
        if ((v) < sec[s]) { \
            thr[s] = sec[s]; \
            if ((v) < best[s]) { sec[s] = best[s]; sidx[s] = bidx[s]; best[s] = (v); bidx[s] = (m); } \
            else { sec[s] = (v); sidx[s] = (m); } \
        } else thr[s] = (v); \
    }

    for (int mc = 0; mc < 8; mc++) {
        if (mc < 7) {
            const char* src = (const char*)(g_bh + ((size_t)(n*8 + mc + 1) << 14));
            uint32_t dbuf = sb + 16384 + (uint32_t)(((mc + 1) & 1) * 32768);
            #pragma unroll
            for (int i = 0; i < 8; i++)
                cp16(dbuf + (tid + i*256)*16, src + (tid + i*256)*16);
            CP_COMMIT();
            CP_WAIT(1);
        } else {
            CP_WAIT(0);
        }
        __syncthreads();

        const uint32_t bufOff = (uint32_t)((mc & 1) * 32768);

        float acc[2][4][4];
        #pragma unroll
        for (int t2 = 0; t2 < 2; t2++)
            #pragma unroll
            for (int mt = 0; mt < 4; mt++)
                #pragma unroll
                for (int c = 0; c < 4; c++) acc[t2][mt][c] = 0.f;

        #pragma unroll
        for (int ks = 0; ks < 8; ks++) {
            const int ks2 = ks * 2;
            uint32_t ah[2][4];
            #pragma unroll
            for (int t2 = 0; t2 < 2; t2++) {
                uint32_t off = (uint32_t)(((ks2 + cqA) ^ a7[t2]) << 4);
                ldsm4(ah[t2], aBase[t2] + off);
            }
            uint32_t bh[2][4];
            #pragma unroll
            for (int p = 0; p < 2; p++) {
                uint32_t off = (uint32_t)(((ks2 + cqB) ^ b7[p]) << 4) + bufOff;
                ldsm4(bh[p], bBase[p] + off);
            }
            #pragma unroll
            for (int t2 = 0; t2 < 2; t2++)
                #pragma unroll
                for (int p = 0; p < 2; p++) {
                    mma_f16(acc[t2][2*p],   ah[t2], &bh[p][0]);
                    mma_f16(acc[t2][2*p+1], ah[t2], &bh[p][2]);
                }
        }

        // epilogue: t = esq - acc/128 ; top-3 insert (m ascending per lane)
        const int mbase = mc*128 + wm*32;
        #pragma unroll
        for (int t2 = 0; t2 < 2; t2++) {
            #pragma unroll
            for (int mt = 0; mt < 4; mt++) {
                float e0 = esq_s[mbase + mt*8 + col2];
                float e1 = esq_s[mbase + mt*8 + col2 + 1];
                int m0 = mbase + mt*8 + col2;
                {
                    const int s = t2*2;
                    float ta = fmaf(acc[t2][mt][0], -0.0078125f, e0);
                    float tb = fmaf(acc[t2][mt][1], -0.0078125f, e1);
                    INS(ta, m0, s);
                    INS(tb, m0 + 1, s);
                }
                {
                    const int s = t2*2 + 1;
                    float ta = fmaf(acc[t2][mt][2], -0.0078125f, e0);
                    float tb = fmaf(acc[t2][mt][3], -0.0078125f, e1);
                    INS(ta, m0, s);
                    INS(tb, m0 + 1, s);
                }
            }
        }
        __syncthreads();
    }
#undef INS

    // quad reduce (lanes sharing lane>>2 hold the same rows)
    #pragma unroll
    for (int s = 0; s < 4; s++) {
        #pragma unroll
        for (int off = 1; off <= 2; off <<= 1) {
            float ob = __shfl_xor_sync(0xffffffffu, best[s], off);
            float os = __shfl_xor_sync(0xffffffffu, sec[s],  off);
            float ot = __shfl_xor_sync(0xffffffffu, thr[s],  off);
            int   oi = __shfl_xor_sync(0xffffffffu, bidx[s], off);
            int   oj = __shfl_xor_sync(0xffffffffu, sidx[s], off);
            mrg3(best[s], sec[s], thr[s], bidx[s], sidx[s], ob, os, ot, oi, oj);
        }
    }
    if ((lane & 3) == 0) {
        const int g = lane >> 2;
        #pragma unroll
        for (int s = 0; s < 4; s++) {
            int row = wl*32 + (s >> 1)*16 + g + (s & 1)*8;
            sb1[wm*64 + row] = best[s];
            sb2[wm*64 + row] = sec[s];
            sb3[wm*64 + row] = thr[s];
            si1[wm*64 + row] = bidx[s];
            si2[wm*64 + row] = sidx[s];
        }
    }
    __syncthreads();

    if (tid < 64) {
        float b1 = sb1[tid], b2 = sb2[tid], b3 = sb3[tid];
        int   i1 = si1[tid], i2 = si2[tid];
        #pragma unroll
        for (int qq = 1; qq < 4; qq++) {
            mrg3(b1, b2, b3, i1, i2,
                 sb1[qq*64 + tid], sb2[qq*64 + tid], sb3[qq*64 + tid],
                 si1[qq*64 + tid], si2[qq*64 + tid]);
        }
        int l = l0 + tid;
        int id = n*LPER + l;
        g_indices[id] = i1;
        // margin: 2^-8 * sqrt(xsq*esqmax) + slack
        float mar = 0.00390625f * sqrtf(g_xsq[id] * __int_as_float(g_esqmaxb[n])) + 2.4e-4f;
        if (b2 - b1 < mar) {
            if (b3 - b1 < mar) {
                int p = atomicAdd(&g_rescnt, 1);
                g_reslist[p] = (n << 14) | l;
            } else {
                int p = atomicAdd(&g_paircnt, 1);
                g_pairlist[p] = make_int2((n << 14) | l, i1 | (i2 << 16));
            }
        }
    }
}

// ---------------- pass 2a: exact pairwise compare ----------------
__global__ void __launch_bounds__(128)
pairfix_kernel(const float* __restrict__ x, const float* __restrict__ emb) {
    __shared__ float xs[64*129];
    __shared__ float Dv[128];
    __shared__ int2  ent[64];
    const int tid = threadIdx.x;
    const int cnt = g_paircnt;

    for (int base = blockIdx.x*64; base < cnt; base += gridDim.x*64) {
        int nent = cnt - base; if (nent > 64) nent = 64;
        if (tid < nent) ent[tid] = g_pairlist[base + tid];
        __syncthreads();
        for (int e = 0; e < nent; e++) {
            int nl = ent[e].x; int n = nl >> 14, l = nl & 16383;
            int b = l >> 6, h = l & 63;
            xs[e*129 + tid] = x[(size_t)b*65536 + (size_t)n*8192 + tid*64 + h];
        }
        __syncthreads();
        if ((tid >> 1) < nent) {
            int e = tid >> 1, c = tid & 1;
            int nl = ent[e].x; int n = nl >> 14, l = nl & 16383;
            int m = c ? (ent[e].y >> 16) : (ent[e].y & 0xffff);
            const float* er = emb + ((size_t)n*1024 + m)*128;
            const float* xr = &xs[e*129];
            float cc = 0.f;
            #pragma unroll 16
            for (int d = 0; d < 128; d++)          // exact ascending-d chain
                cc = fmaf(xr[d], er[d], cc);
            Dv[tid] = __fsub_rn(__fadd_rn(g_esq[n*1024 + m], g_xsq[n*LPER + l]), 2.f*cc);
        }
        __syncthreads();
        if (tid < nent) {
            int m0 = ent[tid].y & 0xffff, m1 = ent[tid].y >> 16;
            float D0 = Dv[2*tid], D1 = Dv[2*tid + 1];
            int win;
            if (D0 < D1) win = m0;
            else if (D1 < D0) win = m1;
            else win = (m0 < m1) ? m0 : m1;
            int nl = ent[tid].x;
            g_indices[(nl >> 14)*LPER + (nl & 16383)] = win;
        }
        __syncthreads();
    }
}

// ---------------- pass 2b: full exact rescan (rare rows) ----------------
__global__ void __launch_bounds__(128)
rescan_kernel(const float* __restrict__ x, const float* __restrict__ emb) {
    __shared__ float xs[128];
    __shared__ unsigned long long keys[128];
    const int tid = threadIdx.x;
    const int cnt = g_rescnt;
    for (int u = blockIdx.x; u < cnt; u += gridDim.x) {
        int nl = g_reslist[u]; int n = nl >> 14, l = nl & 16383;
        int b = l >> 6, h = l & 63;
        xs[tid] = x[(size_t)b*65536 + (size_t)n*8192 + tid*64 + h];
        __syncthreads();
        float xsq = g_xsq[n*LPER + l];
        unsigned long long bk = 0xFFFFFFFFFFFFFFFFull;
        for (int j = 0; j < 8; j++) {
            int m = j*128 + tid;
            const float* er = emb + ((size_t)n*1024 + m)*128;
            float cc = 0.f;
            #pragma unroll 16
            for (int d = 0; d < 128; d++)          // exact ascending-d chain
                cc = fmaf(xs[d], er[d], cc);
            float D = __fsub_rn(__fadd_rn(g_esq[n*1024 + m], xsq), 2.f*cc);
            unsigned ud = __float_as_uint(D);
            ud = (ud & 0x80000000u) ? ~ud : (ud | 0x80000000u);
            unsigned long long key = ((unsigned long long)ud << 32) | (unsigned)m;
            if (key < bk) bk = key;
        }
        keys[tid] = bk;
        __syncthreads();
        for (int st = 64; st; st >>= 1) {
            if (tid < st && keys[tid + st] < keys[tid]) keys[tid] = keys[tid + st];
            __syncthreads();
        }
        if (tid == 0)
            g_indices[n*LPER + l] = (int)(unsigned)(keys[0] & 0xFFFFFFFFull);
        __syncthreads();
    }
}

// ---------------- gather + z_q + loss partials + indices out (float4) ----------------
__global__ void __launch_bounds__(256)
gather_kernel(const float* __restrict__ x, const float* __restrict__ emb,
              float* __restrict__ out, float* __restrict__ out_idx, int write_extras) {
    __shared__ int   midx[64];
    __shared__ float rows[64*129];
    __shared__ float red[256];
    const int n = blockIdx.x & 7, b = blockIdx.x >> 3, tid = threadIdx.x;

    if (tid < 64) {
        int m = g_indices[n*LPER + b*HLAT + tid];
        midx[tid] = m;
        if (write_extras) out_idx[b*(NCB*HLAT) + n*HLAT + tid] = (float)m;
    }
    __syncthreads();
    for (int idx = tid; idx < 64*32; idx += 256) {
        int r = idx >> 5, dq = (idx & 31) * 4;
        float4 v = *(const float4*)&emb[((size_t)n*MEMB + midx[r])*DEMB + dq];
        float* dst = &rows[r*129 + dq];
        dst[0] = v.x; dst[1] = v.y; dst[2] = v.z; dst[3] = v.w;
    }
    __syncthreads();
    float s = 0.f;
    const size_t base = (size_t)b*65536 + (size_t)n*8192;
    for (int idx4 = tid; idx4 < 2048; idx4 += 256) {
        int d = idx4 >> 4, h4 = (idx4 & 15) * 4;
        float4 q;
        q.x = rows[(h4+0)*129 + d];
        q.y = rows[(h4+1)*129 + d];
        q.z = rows[(h4+2)*129 + d];
        q.w = rows[(h4+3)*129 + d];
        float4 xv = *(const float4*)&x[base + d*64 + h4];
        *(float4*)&out[base + d*64 + h4] = q;
        float dx = xv.x - q.x, dy = xv.y - q.y, dz = xv.z - q.z, dw = xv.w - q.w;
        s += dx*dx + dy*dy + dz*dz + dw*dw;
    }
    red[tid] = s;
    __syncthreads();
    for (int st = 128; st; st >>= 1) { if (tid < st) red[tid] += red[tid+st]; __syncthreads(); }
    if (tid == 0) g_part[blockIdx.x] = red[0];
}

// ---------------- entropy ----------------
__global__ void entropy_kernel() {
    __shared__ int   hist[MEMB];
    __shared__ float red[256];
    const int n = blockIdx.x, tid = threadIdx.x;
    for (int i = tid; i < MEMB; i += 256) hist[i] = 0;
    __syncthreads();
    for (int l = tid; l < LPER; l += 256) atomicAdd(&hist[g_indices[n*LPER + l]], 1);
    __syncthreads();
    float s = 0.f;
    for (int m = tid; m < MEMB; m += 256) {
        float p = (float)hist[m] * (1.f / (float)LPER);
        s += p * logf(p + 1e-10f);
    }
    red[tid] = s;
    __syncthreads();
    for (int st = 128; st; st >>= 1) { if (tid < st) red[tid] += red[tid+st]; __syncthreads(); }
    if (tid == 0) g_ent[n] = -red[0];
}

// ---------------- finalize ----------------
__global__ void finalize_kernel(float* __restrict__ out, int write_scalars) {
    __shared__ float red[256];
    const int tid = threadIdx.x;
    float s = 0.f;
    for (int i = tid; i < 2048; i += 256) s += g_part[i];
    red[tid] = s;
    __syncthreads();
    for (int st = 128; st; st >>= 1) { if (tid < st) red[tid] += red[tid+st]; __syncthreads(); }
    if (tid == 0 && write_scalars) {
        float loss = 0.25f * red[0] / (float)ZQ_ELEMS;
        float ent = 0.f, perp = 0.f;
        #pragma unroll
        for (int n = 0; n < NCB; n++) { ent += g_ent[n]; perp += expf(g_ent[n]); }
        out[ZQ_ELEMS + 0] = loss;
        out[ZQ_ELEMS + 1] = ent * (1.f / NCB);
        out[ZQ_ELEMS + 2] = perp * (1.f / NCB);
    }
}

// ---------------- launch ----------------
extern "C" void kernel_launch(void* const* d_in, const int* in_sizes, int n_in,
                              void* d_out, int out_size) {
    const float* x   = (const float*)d_in[0];
    const float* emb = (const float*)d_in[1];
    if (n_in >= 2 && in_sizes[0] == NCB*MEMB*DEMB && in_sizes[1] == ZQ_ELEMS) {
        const float* t = x; x = emb; emb = t;
    }
    float* out = (float*)d_out;
    const int full = (out_size >= ZQ_ELEMS + 3 + IDX_ELEMS) ? 1 : 0;

    const int SMEM_ARG = 91136 + 1024;
    cudaFuncSetAttribute(argmin_mma, cudaFuncAttributeMaxDynamicSharedMemorySize, SMEM_ARG);

    esq_kernel<<<(NCB*MEMB + 255)/256, 256>>>(emb);
    xsq_kernel<<<BATCH*NCB, 256>>>(x);
    bprep_kernel<<<(NCB*MEMB*DEMB + 255)/256, 256>>>(emb);
    argmin_mma<<<NCB * (LPER/64), 256, SMEM_ARG>>>(x);
    pairfix_kernel<<<512, 128>>>(x, emb);
    rescan_kernel<<<512, 128>>>(x, emb);
    gather_kernel<<<BATCH*NCB, 256>>>(x, emb, out, out + ZQ_ELEMS + 3, full);
    entropy_kernel<<<NCB, 256>>>();
    finalize_kernel<<<1, 256>>>(out, full);
}

// round 13
// speedup vs baseline: 2.4910x; 2.4910x over previous
#include <cuda_runtime.h>
#include <cuda_fp16.h>
#include <math.h>
#include <stdint.h>

#define NCB   8
#define MEMB  1024
#define DEMB  128
#define HLAT  64
#define BATCH 256
#define LPER  (BATCH*HLAT)              /* 16384 per codebook */
#define ZQ_ELEMS (BATCH*NCB*DEMB*HLAT)  /* 16777216 */
#define IDX_ELEMS (BATCH*NCB*HLAT)      /* 131072 */

// ---------------- device scratch ----------------
__device__ int   g_indices[NCB*LPER];
__device__ float g_esq[NCB*MEMB];
__device__ int   g_esqmaxb[NCB];
__device__ float g_xsq[NCB*LPER];
__device__ float g_part[2048];
__device__ float g_ent[NCB];
__device__ int   g_paircnt;
__device__ int2  g_pairlist[NCB*LPER];        // .x=(n<<14)|l, .y=i1|(i2<<16)
__device__ float g_xpp[(size_t)NCB*LPER*DEMB]; // packed x rows for pair entries
__device__ int   g_rcnt[NCB];                  // per-codebook rescan counts
__device__ int   g_rlist[NCB*LPER];            // per-codebook rescan l values
__device__ float g_xpr[(size_t)NCB*LPER*DEMB]; // packed x rows for rescan (per n,slot)
__device__ unsigned long long g_fixkey[NCB*LPER];
// pre-swizzled fp16 embedding tiles (e*256): [n][mchunk 8][row 128][k 128]
__device__ __half g_bh[NCB*MEMB*DEMB];

// ---------------- PTX helpers ----------------
__device__ __forceinline__ uint32_t smem_u32(const void* p) {
    uint32_t a;
    asm("{ .reg .u64 t; cvta.to.shared.u64 t, %1; cvt.u32.u64 %0, t; }" : "=r"(a) : "l"(p));
    return a;
}
__device__ __forceinline__ void ldsm4(uint32_t* r, uint32_t addr) {
    asm volatile("ldmatrix.sync.aligned.m8n8.x4.shared.b16 {%0,%1,%2,%3}, [%4];"
        : "=r"(r[0]), "=r"(r[1]), "=r"(r[2]), "=r"(r[3]) : "r"(addr));
}
__device__ __forceinline__ void mma_f16(float* c, const uint32_t* a, const uint32_t* b) {
    asm volatile("mma.sync.aligned.m16n8k16.row.col.f32.f16.f16.f32 "
        "{%0,%1,%2,%3}, {%4,%5,%6,%7}, {%8,%9}, {%0,%1,%2,%3};"
        : "+f"(c[0]), "+f"(c[1]), "+f"(c[2]), "+f"(c[3])
        : "r"(a[0]), "r"(a[1]), "r"(a[2]), "r"(a[3]), "r"(b[0]), "r"(b[1]));
}
__device__ __forceinline__ void cp16(uint32_t dst, const void* src) {
    asm volatile("cp.async.cg.shared.global [%0], [%1], 16;" :: "r"(dst), "l"(src) : "memory");
}
#define CP_COMMIT() asm volatile("cp.async.commit_group;" ::: "memory")
#define CP_WAIT(n)  asm volatile("cp.async.wait_group %0;" :: "n"(n) : "memory")

// merge two sorted top-3 triples (values asc; indices for first two)
__device__ __forceinline__ void mrg3(float& a1, float& a2, float& a3, int& i1, int& i2,
                                     float b1, float b2, float b3, int j1, int j2) {
    if (b1 < a1 || (b1 == a1 && j1 < i1)) {
        float v; int t;
        v = a1; a1 = b1; b1 = v;  t = i1; i1 = j1; j1 = t;
        v = a2; a2 = b2; b2 = v;  t = i2; i2 = j2; j2 = t;
        v = a3; a3 = b3; b3 = v;
    }
    if (b1 < a2 || (b1 == a2 && j1 < i2)) {
        a3 = fminf(a2, b2);
        a2 = b1; i2 = j1;
    } else {
        a3 = fminf(a3, b1);
    }
}

// ---------------- e_sq (exact sequential) + per-n max + counter reset ----------------
__global__ void esq_kernel(const float* __restrict__ emb) {
    int t = blockIdx.x * blockDim.x + threadIdx.x;
    if (t == 0) g_paircnt = 0;
    if (t < NCB) g_rcnt[t] = 0;
    if (t >= NCB*MEMB) return;
    const float* row = emb + (size_t)t * DEMB;
    float acc = 0.f;
    #pragma unroll 8
    for (int d = 0; d < DEMB; d++) {
        float v = row[d];
        acc = __fadd_rn(acc, __fmul_rn(v, v));
    }
    g_esq[t] = acc;
    atomicMax(&g_esqmaxb[t >> 10], __float_as_int(acc));
}

// ---------------- x_sq (exact sequential) ----------------
__global__ void __launch_bounds__(256)
xsq_kernel(const float* __restrict__ x) {
    __shared__ float tile[8192];
    const int n = blockIdx.x & 7, b = blockIdx.x >> 3, tid = threadIdx.x;
    const size_t base = (size_t)b*65536 + (size_t)n*8192;
    for (int i = tid; i < 8192; i += 256) tile[i] = x[base + i];
    __syncthreads();
    if (tid < 64) {
        float acc = 0.f;
        #pragma unroll 8
        for (int d = 0; d < DEMB; d++) {
            float v = tile[d*64 + tid];
            acc = __fadd_rn(acc, __fmul_rn(v, v));
        }
        g_xsq[n*LPER + b*HLAT + tid] = acc;
    }
}

// ---------------- embedding -> swizzled fp16 (e*256) tiles ----------------
__global__ void bprep_kernel(const float* __restrict__ emb) {
    int u = blockIdx.x * blockDim.x + threadIdx.x;
    if (u >= NCB*MEMB*DEMB) return;
    float v = emb[u] * 256.0f;
    int d = u & 127, m = (u >> 7) & 1023, n = u >> 17;
    int row = m & 127, mc = m >> 7;
    int elem = ((n*8 + mc)*128 + row)*128 + (((d >> 3) ^ (row & 7)) << 3) + (d & 7);
    g_bh[elem] = __float2half_rn(v);
}

// ---------------- pass 1: fp16 1-MMA approximate argmin with top-3 ----------------
__global__ void __launch_bounds__(256, 2)
argmin_mma(const float* __restrict__ x) {
    extern __shared__ char smraw[];
    uint32_t sraw = smem_u32(smraw);
    uint32_t sb = (sraw + 1023u) & ~1023u;
    char* sm = smraw + (sb - sraw);
    __half* Ahi = (__half*)(sm);              // 16KB @0
    // B buffers: buf0 @16384 (32KB), buf1 @49152 (32KB)
    float* esq_s = (float*)(sm + 81920);
    float* sb1 = (float*)(sm + 86016);
    float* sb2 = (float*)(sm + 87040);
    float* sb3 = (float*)(sm + 88064);
    int*   si1 = (int*)  (sm + 89088);
    int*   si2 = (int*)  (sm + 90112);

    const int n  = blockIdx.x >> 8;
    const int lt = blockIdx.x & 255;
    const int l0 = lt * 64;
    const int tid  = threadIdx.x;
    const int lane = tid & 31;
    const int w    = tid >> 5;
    const int wl   = w & 1;
    const int wm   = w >> 1;

    {
        const char* src = (const char*)(g_bh + ((size_t)(n*8 + 0) << 14));
        uint32_t dst = sb + 16384;
        #pragma unroll
        for (int i = 0; i < 8; i++)
            cp16(dst + (tid + i*256)*16, src + (tid + i*256)*16);
        CP_COMMIT();
    }

    for (int i = tid; i < 1024; i += 256) esq_s[i] = g_esq[n*1024 + i];

    for (int idx = tid; idx < 8192; idx += 256) {
        int d = idx >> 6, j = idx & 63;
        float v = x[(size_t)lt*65536 + (size_t)n*8192 + d*64 + j];
        int elem = j*128 + (((d >> 3) ^ (j & 7)) << 3) + (d & 7);
        Ahi[elem] = __float2half_rn(v);
    }

    const uint32_t sAh = sb, sBh0 = sb + 16384;
    const int q  = lane >> 3;
    const int r8 = lane & 7;
    const int cqA = q >> 1;
    const int cqB = q & 1;
    uint32_t aBase[2]; int a7[2];
    #pragma unroll
    for (int t2 = 0; t2 < 2; t2++) {
        int rowA = wl*32 + t2*16 + r8 + (q & 1)*8;
        aBase[t2] = sAh + rowA*256; a7[t2] = rowA & 7;
    }
    uint32_t bBase[2]; int b7[2];
    #pragma unroll
    for (int p = 0; p < 2; p++) {
        int rowB = wm*32 + p*16 + r8 + (q >> 1)*8;
        bBase[p] = sBh0 + rowB*256; b7[p] = rowB & 7;
    }

    float best[4], sec[4], thr[4];
    int   bidx[4], sidx[4];
    #pragma unroll
    for (int s = 0; s < 4; s++) {
        best[s] = 3.4e38f; sec[s] = 3.4e38f; thr[s] = 3.4e38f;
        bidx[s] = 0; sidx[s] = 0;
    }

    const int col2 = (lane & 3) * 2;

#define INS(v, m, s) \
    if ((v) < thr[s]) { \
        if ((v) < sec[s]) { \
            thr[s] = sec[s]; \
            if ((v) < best[s]) { sec[s] = best[s]; sidx[s] = bidx[s]; best[s] = (v); bidx[s] = (m); } \
            else { sec[s] = (v); sidx[s] = (m); } \
        } else thr[s] = (v); \
    }

    for (int mc = 0; mc < 8; mc++) {
        if (mc < 7) {
            const char* src = (const char*)(g_bh + ((size_t)(n*8 + mc + 1) << 14));
            uint32_t dbuf = sb + 16384 + (uint32_t)(((mc + 1) & 1) * 32768);
            #pragma unroll
            for (int i = 0; i < 8; i++)
                cp16(dbuf + (tid + i*256)*16, src + (tid + i*256)*16);
            CP_COMMIT();
            CP_WAIT(1);
        } else {
            CP_WAIT(0);
        }
        __syncthreads();

        const uint32_t bufOff = (uint32_t)((mc & 1) * 32768);

        float acc[2][4][4];
        #pragma unroll
        for (int t2 = 0; t2 < 2; t2++)
            #pragma unroll
            for (int mt = 0; mt < 4; mt++)
                #pragma unroll
                for (int c = 0; c < 4; c++) acc[t2][mt][c] = 0.f;

        #pragma unroll
        for (int ks = 0; ks < 8; ks++) {
            const int ks2 = ks * 2;
            uint32_t ah[2][4];
            #pragma unroll
            for (int t2 = 0; t2 < 2; t2++) {
                uint32_t off = (uint32_t)(((ks2 + cqA) ^ a7[t2]) << 4);
                ldsm4(ah[t2], aBase[t2] + off);
            }
            uint32_t bh[2][4];
            #pragma unroll
            for (int p = 0; p < 2; p++) {
                uint32_t off = (uint32_t)(((ks2 + cqB) ^ b7[p]) << 4) + bufOff;
                ldsm4(bh[p], bBase[p] + off);
            }
            #pragma unroll
            for (int t2 = 0; t2 < 2; t2++)
                #pragma unroll
                for (int p = 0; p < 2; p++) {
                    mma_f16(acc[t2][2*p],   ah[t2], &bh[p][0]);
                    mma_f16(acc[t2][2*p+1], ah[t2], &bh[p][2]);
                }
        }

        const int mbase = mc*128 + wm*32;
        #pragma unroll
        for (int t2 = 0; t2 < 2; t2++) {
            #pragma unroll
            for (int mt = 0; mt < 4; mt++) {
                float e0 = esq_s[mbase + mt*8 + col2];
                float e1 = esq_s[mbase + mt*8 + col2 + 1];
                int m0 = mbase + mt*8 + col2;
                {
                    const int s = t2*2;
                    float ta = fmaf(acc[t2][mt][0], -0.0078125f, e0);
                    float tb = fmaf(acc[t2][mt][1], -0.0078125f, e1);
                    INS(ta, m0, s);
                    INS(tb, m0 + 1, s);
                }
                {
                    const int s = t2*2 + 1;
                    float ta = fmaf(acc[t2][mt][2], -0.0078125f, e0);
                    float tb = fmaf(acc[t2][mt][3], -0.0078125f, e1);
                    INS(ta, m0, s);
                    INS(tb, m0 + 1, s);
                }
            }
        }
        __syncthreads();
    }
#undef INS

    #pragma unroll
    for (int s = 0; s < 4; s++) {
        #pragma unroll
        for (int off = 1; off <= 2; off <<= 1) {
            float ob = __shfl_xor_sync(0xffffffffu, best[s], off);
            float os = __shfl_xor_sync(0xffffffffu, sec[s],  off);
            float ot = __shfl_xor_sync(0xffffffffu, thr[s],  off);
            int   oi = __shfl_xor_sync(0xffffffffu, bidx[s], off);
            int   oj = __shfl_xor_sync(0xffffffffu, sidx[s], off);
            mrg3(best[s], sec[s], thr[s], bidx[s], sidx[s], ob, os, ot, oi, oj);
        }
    }
    if ((lane & 3) == 0) {
        const int g = lane >> 2;
        #pragma unroll
        for (int s = 0; s < 4; s++) {
            int row = wl*32 + (s >> 1)*16 + g + (s & 1)*8;
            sb1[wm*64 + row] = best[s];
            sb2[wm*64 + row] = sec[s];
            sb3[wm*64 + row] = thr[s];
            si1[wm*64 + row] = bidx[s];
            si2[wm*64 + row] = sidx[s];
        }
    }
    __syncthreads();

    if (tid < 64) {
        float b1 = sb1[tid], b2 = sb2[tid], b3 = sb3[tid];
        int   i1 = si1[tid], i2 = si2[tid];
        #pragma unroll
        for (int qq = 1; qq < 4; qq++) {
            mrg3(b1, b2, b3, i1, i2,
                 sb1[qq*64 + tid], sb2[qq*64 + tid], sb3[qq*64 + tid],
                 si1[qq*64 + tid], si2[qq*64 + tid]);
        }
        int l = l0 + tid;
        int id = n*LPER + l;
        g_indices[id] = i1;
        float mar = 0.00390625f * sqrtf(g_xsq[id] * __int_as_float(g_esqmaxb[n])) + 2.4e-4f;
        if (b2 - b1 < mar) {
            if (b3 - b1 < mar) {
                g_fixkey[id] = 0xFFFFFFFFFFFFFFFFull;
                int p = atomicAdd(&g_rcnt[n], 1);
                g_rlist[n*LPER + p] = l;
            } else {
                int p = atomicAdd(&g_paircnt, 1);
                g_pairlist[p] = make_int2((n << 14) | l, i1 | (i2 << 16));
            }
        }
    }
}

// ---------------- pack pair x rows (one block per row, single iteration) ----------------
__global__ void __launch_bounds__(128)
packP_kernel(const float* __restrict__ x) {
    const int cnt = g_paircnt;
    for (int u = blockIdx.x; u < cnt; u += gridDim.x) {
        int nl = g_pairlist[u].x;
        int n = nl >> 14, l = nl & 16383;
        int b = l >> 6, h = l & 63;
        g_xpp[(size_t)u*128 + threadIdx.x] =
            x[(size_t)b*65536 + (size_t)n*8192 + threadIdx.x*64 + h];
    }
}

// ---------------- pack rescan x rows (per-codebook lists) ----------------
__global__ void __launch_bounds__(128)
packR_kernel(const float* __restrict__ x) {
    const int n = blockIdx.y;
    const int cnt = g_rcnt[n];
    for (int p = blockIdx.x; p < cnt; p += gridDim.x) {
        int l = g_rlist[n*LPER + p];
        int b = l >> 6, h = l & 63;
        g_xpr[((size_t)n*LPER + p)*128 + threadIdx.x] =
            x[(size_t)b*65536 + (size_t)n*8192 + threadIdx.x*64 + h];
    }
}

// ---------------- pass 2a: exact pairwise compare (128 entries/block) ----------------
__global__ void __launch_bounds__(256)
pairfix_kernel(const float* __restrict__ emb) {
    extern __shared__ float xsf[];            // [128 entries][stride 132]
    __shared__ float Dv[256];
    __shared__ int2  ent[128];
    const int tid = threadIdx.x;
    const int cnt = g_paircnt;

    for (int base = blockIdx.x*128; base < cnt; base += gridDim.x*128) {
        int nent = cnt - base; if (nent > 128) nent = 128;
        if (tid < nent) ent[tid] = g_pairlist[base + tid];
        __syncthreads();
        // stage xs coalesced from packed buffer (float4)
        for (int i = tid; i < nent*32; i += 256) {
            int e = i >> 5, qv = (i & 31) * 4;
            float4 v = *(const float4*)&g_xpp[(size_t)(base + e)*128 + qv];
            float* dst = &xsf[e*132 + qv];
            dst[0] = v.x; dst[1] = v.y; dst[2] = v.z; dst[3] = v.w;
        }
        __syncthreads();
        if ((tid >> 1) < nent) {
            int e = tid >> 1, c = tid & 1;
            int nl = ent[e].x; int n = nl >> 14, l = nl & 16383;
            int m = c ? (ent[e].y >> 16) : (ent[e].y & 0xffff);
            const float4* er4 = (const float4*)(emb + ((size_t)n*1024 + m)*128);
            const float* xr = &xsf[e*132];
            float cc = 0.f;
            #pragma unroll 8
            for (int qq = 0; qq < 32; qq++) {   // exact ascending-d chain
                float4 e4 = er4[qq];
                cc = fmaf(xr[qq*4+0], e4.x, cc);
                cc = fmaf(xr[qq*4+1], e4.y, cc);
                cc = fmaf(xr[qq*4+2], e4.z, cc);
                cc = fmaf(xr[qq*4+3], e4.w, cc);
            }
            Dv[tid] = __fsub_rn(__fadd_rn(g_esq[n*1024 + m], g_xsq[n*LPER + l]), 2.f*cc);
        }
        __syncthreads();
        if (tid < nent) {
            int m0 = ent[tid].y & 0xffff, m1 = ent[tid].y >> 16;
            float D0 = Dv[2*tid], D1 = Dv[2*tid + 1];
            int win;
            if (D0 < D1) win = m0;
            else if (D1 < D0) win = m1;
            else win = (m0 < m1) ? m0 : m1;
            int nl = ent[tid].x;
            g_indices[(nl >> 14)*LPER + (nl & 16383)] = win;
        }
        __syncthreads();
    }
}

// ---------------- pass 2b: full exact rescan, E staged in smem (R11-proven) ----------------
__global__ void __launch_bounds__(128)
rescan_kernel(const float* __restrict__ emb) {
    extern __shared__ float fsm[];
    float* E     = fsm;                       // [128 codes][stride 132]
    float* xs    = fsm + 128*132;             // [8 rows][128]
    float* esq_c = xs + 1024;                 // [128]
    float* xsq_s = esq_c + 128;               // [8]
    unsigned long long* wred = (unsigned long long*)(xsq_s + 8);   // [4][8]

    const int n     = blockIdx.x >> 7;
    const int mc    = (blockIdx.x >> 4) & 7;
    const int slice = blockIdx.x & 15;
    const int tid   = threadIdx.x;
    const int wid   = tid >> 5, lane = tid & 31;

    const int cnt = g_rcnt[n];
    if (cnt == 0) return;

    const float* src = emb + ((size_t)n*1024 + mc*128)*128;
    for (int i = tid; i < 16384; i += 128) {
        int r = i >> 7, d = i & 127;
        E[r*132 + d] = src[i];
    }
    esq_c[tid] = g_esq[n*1024 + mc*128 + tid];
    __syncthreads();

    const unsigned code_m = (unsigned)(mc*128 + tid);

    for (int g0 = slice*8; g0 < cnt; g0 += 16*8) {
        #pragma unroll
        for (int r = 0; r < 8; r++) {
            int u = g0 + r;
            int uc = (u < cnt) ? u : (cnt - 1);
            xs[r*128 + tid] = g_xpr[((size_t)n*LPER + uc)*128 + tid];
        }
        if (tid < 8) {
            int u = g0 + tid;
            int uc = (u < cnt) ? u : (cnt - 1);
            xsq_s[tid] = g_xsq[n*LPER + g_rlist[n*LPER + uc]];
        }
        __syncthreads();

        float c[8];
        #pragma unroll
        for (int r = 0; r < 8; r++) c[r] = 0.f;
        const float4* er4 = (const float4*)&E[tid*132];
        #pragma unroll 8
        for (int qq = 0; qq < 32; qq++) {
            float4 e = er4[qq];
            #pragma unroll
            for (int r = 0; r < 8; r++) {
                float4 xr = *(const float4*)&xs[r*128 + qq*4];
                c[r] = fmaf(xr.x, e.x, c[r]);
                c[r] = fmaf(xr.y, e.y, c[r]);
                c[r] = fmaf(xr.z, e.z, c[r]);
                c[r] = fmaf(xr.w, e.w, c[r]);
            }
        }

        #pragma unroll
        for (int r = 0; r < 8; r++) {
            float D = __fsub_rn(__fadd_rn(esq_c[tid], xsq_s[r]), 2.f*c[r]);
            unsigned ud = __float_as_uint(D);
            ud = (ud & 0x80000000u) ? ~ud : (ud | 0x80000000u);
            unsigned long long key = ((unsigned long long)ud << 32) | code_m;
            #pragma unroll
            for (int o = 16; o; o >>= 1) {
                unsigned long long ok = __shfl_xor_sync(0xffffffffu, key, o);
                if (ok < key) key = ok;
            }
            if (lane == 0) wred[wid*8 + r] = key;
        }
        __syncthreads();
        if (tid < 8) {
            int u = g0 + tid;
            if (u < cnt) {
                unsigned long long k = wred[tid];
                if (wred[8  + tid] < k) k = wred[8  + tid];
                if (wred[16 + tid] < k) k = wred[16 + tid];
                if (wred[24 + tid] < k) k = wred[24 + tid];
                int l = g_rlist[n*LPER + u];
                atomicMin(&g_fixkey[n*LPER + l], k);
            }
        }
        __syncthreads();
    }
}

// ---------------- unpack rescan indices ----------------
__global__ void unpack_kernel() {
    const int n = blockIdx.x;
    const int cnt = g_rcnt[n];
    for (int p = threadIdx.x; p < cnt; p += blockDim.x) {
        int l = g_rlist[n*LPER + p];
        int id = n*LPER + l;
        g_indices[id] = (int)(unsigned)(g_fixkey[id] & 0xFFFFFFFFull);
    }
}

// ---------------- gather + z_q + loss partials + indices out (float4) ----------------
__global__ void __launch_bounds__(256)
gather_kernel(const float* __restrict__ x, const float* __restrict__ emb,
              float* __restrict__ out, float* __restrict__ out_idx, int write_extras) {
    __shared__ int   midx[64];
    __shared__ float rows[64*129];
    __shared__ float red[256];
    const int n = blockIdx.x & 7, b = blockIdx.x >> 3, tid = threadIdx.x;

    if (tid < 64) {
        int m = g_indices[n*LPER + b*HLAT + tid];
        midx[tid] = m;
        if (write_extras) out_idx[b*(NCB*HLAT) + n*HLAT + tid] = (float)m;
    }
    __syncthreads();
    for (int idx = tid; idx < 64*32; idx += 256) {
        int r = idx >> 5, dq = (idx & 31) * 4;
        float4 v = *(const float4*)&emb[((size_t)n*MEMB + midx[r])*DEMB + dq];
        float* dst = &rows[r*129 + dq];
        dst[0] = v.x; dst[1] = v.y; dst[2] = v.z; dst[3] = v.w;
    }
    __syncthreads();
    float s = 0.f;
    const size_t base = (size_t)b*65536 + (size_t)n*8192;
    for (int idx4 = tid; idx4 < 2048; idx4 += 256) {
        int d = idx4 >> 4, h4 = (idx4 & 15) * 4;
        float4 q;
        q.x = rows[(h4+0)*129 + d];
        q.y = rows[(h4+1)*129 + d];
        q.z = rows[(h4+2)*129 + d];
        q.w = rows[(h4+3)*129 + d];
        float4 xv = *(const float4*)&x[base + d*64 + h4];
        *(float4*)&out[base + d*64 + h4] = q;
        float dx = xv.x - q.x, dy = xv.y - q.y, dz = xv.z - q.z, dw = xv.w - q.w;
        s += dx*dx + dy*dy + dz*dz + dw*dw;
    }
    red[tid] = s;
    __syncthreads();
    for (int st = 128; st; st >>= 1) { if (tid < st) red[tid] += red[tid+st]; __syncthreads(); }
    if (tid == 0) g_part[blockIdx.x] = red[0];
}

// ---------------- entropy ----------------
__global__ void entropy_kernel() {
    __shared__ int   hist[MEMB];
    __shared__ float red[256];
    const int n = blockIdx.x, tid = threadIdx.x;
    for (int i = tid; i < MEMB; i += 256) hist[i] = 0;
    __syncthreads();
    for (int l = tid; l < LPER; l += 256) atomicAdd(&hist[g_indices[n*LPER + l]], 1);
    __syncthreads();
    float s = 0.f;
    for (int m = tid; m < MEMB; m += 256) {
        float p = (float)hist[m] * (1.f / (float)LPER);
        s += p * logf(p + 1e-10f);
    }
    red[tid] = s;
    __syncthreads();
    for (int st = 128; st; st >>= 1) { if (tid < st) red[tid] += red[tid+st]; __syncthreads(); }
    if (tid == 0) g_ent[n] = -red[0];
}

// ---------------- finalize ----------------
__global__ void finalize_kernel(float* __restrict__ out, int write_scalars) {
    __shared__ float red[256];
    const int tid = threadIdx.x;
    float s = 0.f;
    for (int i = tid; i < 2048; i += 256) s += g_part[i];
    red[tid] = s;
    __syncthreads();
    for (int st = 128; st; st >>= 1) { if (tid < st) red[tid] += red[tid+st]; __syncthreads(); }
    if (tid == 0 && write_scalars) {
        float loss = 0.25f * red[0] / (float)ZQ_ELEMS;
        float ent = 0.f, perp = 0.f;
        #pragma unroll
        for (int n = 0; n < NCB; n++) { ent += g_ent[n]; perp += expf(g_ent[n]); }
        out[ZQ_ELEMS + 0] = loss;
        out[ZQ_ELEMS + 1] = ent * (1.f / NCB);
        out[ZQ_ELEMS + 2] = perp * (1.f / NCB);
    }
}

// ---------------- launch ----------------
extern "C" void kernel_launch(void* const* d_in, const int* in_sizes, int n_in,
                              void* d_out, int out_size) {
    const float* x   = (const float*)d_in[0];
    const float* emb = (const float*)d_in[1];
    if (n_in >= 2 && in_sizes[0] == NCB*MEMB*DEMB && in_sizes[1] == ZQ_ELEMS) {
        const float* t = x; x = emb; emb = t;
    }
    float* out = (float*)d_out;
    const int full = (out_size >= ZQ_ELEMS + 3 + IDX_ELEMS) ? 1 : 0;

    const int SMEM_ARG = 91136 + 1024;
    cudaFuncSetAttribute(argmin_mma, cudaFuncAttributeMaxDynamicSharedMemorySize, SMEM_ARG);
    const int SMEM_PAIR = 128*132*4;                                  // 67584
    cudaFuncSetAttribute(pairfix_kernel, cudaFuncAttributeMaxDynamicSharedMemorySize, SMEM_PAIR);
    const int SMEM_RES = (128*132 + 8*128 + 128 + 8) * 4 + 32 * 8;    // 72480
    cudaFuncSetAttribute(rescan_kernel, cudaFuncAttributeMaxDynamicSharedMemorySize, SMEM_RES);

    esq_kernel<<<(NCB*MEMB + 255)/256, 256>>>(emb);
    xsq_kernel<<<BATCH*NCB, 256>>>(x);
    bprep_kernel<<<(NCB*MEMB*DEMB + 255)/256, 256>>>(emb);
    argmin_mma<<<NCB * (LPER/64), 256, SMEM_ARG>>>(x);
    packP_kernel<<<2048, 128>>>(x);
    packR_kernel<<<dim3(256, NCB), 128>>>(x);
    pairfix_kernel<<<296, 256, SMEM_PAIR>>>(emb);
    rescan_kernel<<<NCB*8*16, 128, SMEM_RES>>>(emb);
    unpack_kernel<<<NCB, 256>>>();
    gather_kernel<<<BATCH*NCB, 256>>>(x, emb, out, out + ZQ_ELEMS + 3, full);
    entropy_kernel<<<NCB, 256>>>();
    finalize_kernel<<<1, 256>>>(out, full);
}

// round 14
// speedup vs baseline: 2.8483x; 1.1434x over previous
#include <cuda_runtime.h>
#include <cuda_fp16.h>
#include <math.h>
#include <stdint.h>

#define NCB   8
#define MEMB  1024
#define DEMB  128
#define HLAT  64
#define BATCH 256
#define LPER  (BATCH*HLAT)              /* 16384 per codebook */
#define ZQ_ELEMS (BATCH*NCB*DEMB*HLAT)  /* 16777216 */
#define IDX_ELEMS (BATCH*NCB*HLAT)      /* 131072 */

// ---------------- device scratch ----------------
__device__ int   g_indices[NCB*LPER];
__device__ float g_esq[NCB*MEMB];
__device__ int   g_esqmaxb[NCB];
__device__ float g_xsq[NCB*LPER];
__device__ float g_part[2048];
__device__ float g_ent[NCB];
__device__ int   g_paircnt;
__device__ int2  g_pairlist[NCB*LPER];        // .x=(n<<14)|l, .y=i1|(i2<<16)
__device__ float g_xpp[(size_t)NCB*LPER*DEMB]; // packed x rows for pair entries
__device__ int   g_rcnt[NCB];
__device__ int   g_rlist[NCB*LPER];
__device__ float g_xpr[(size_t)NCB*LPER*DEMB];
__device__ unsigned long long g_fixkey[NCB*LPER];
// pre-swizzled fp16 embedding tiles (e*256): [n][mchunk 16][row 64][k 128]
__device__ __half g_bh[NCB*MEMB*DEMB];

// ---------------- PTX helpers ----------------
__device__ __forceinline__ uint32_t smem_u32(const void* p) {
    uint32_t a;
    asm("{ .reg .u64 t; cvta.to.shared.u64 t, %1; cvt.u32.u64 %0, t; }" : "=r"(a) : "l"(p));
    return a;
}
__device__ __forceinline__ void ldsm4(uint32_t* r, uint32_t addr) {
    asm volatile("ldmatrix.sync.aligned.m8n8.x4.shared.b16 {%0,%1,%2,%3}, [%4];"
        : "=r"(r[0]), "=r"(r[1]), "=r"(r[2]), "=r"(r[3]) : "r"(addr));
}
__device__ __forceinline__ void mma_f16(float* c, const uint32_t* a, const uint32_t* b) {
    asm volatile("mma.sync.aligned.m16n8k16.row.col.f32.f16.f16.f32 "
        "{%0,%1,%2,%3}, {%4,%5,%6,%7}, {%8,%9}, {%0,%1,%2,%3};"
        : "+f"(c[0]), "+f"(c[1]), "+f"(c[2]), "+f"(c[3])
        : "r"(a[0]), "r"(a[1]), "r"(a[2]), "r"(a[3]), "r"(b[0]), "r"(b[1]));
}
__device__ __forceinline__ void cp16(uint32_t dst, const void* src) {
    asm volatile("cp.async.cg.shared.global [%0], [%1], 16;" :: "r"(dst), "l"(src) : "memory");
}
#define CP_COMMIT() asm volatile("cp.async.commit_group;" ::: "memory")
#define CP_WAIT(n)  asm volatile("cp.async.wait_group %0;" :: "n"(n) : "memory")

// merge two sorted uint triples (7 min/max ops)
__device__ __forceinline__ void kmrg(uint32_t& a1, uint32_t& a2, uint32_t& a3,
                                     uint32_t b1, uint32_t b2, uint32_t b3) {
    uint32_t M  = max(a1, b1);
    uint32_t m2 = min(a2, b2);
    uint32_t r1 = min(a1, b1);
    uint32_t r2 = min(M, m2);
    uint32_t r3 = min(min(a3, b3), max(m2, M));
    a1 = r1; a2 = r2; a3 = r3;
}

// ---------------- e_sq (exact sequential) + per-n max + counter reset ----------------
__global__ void esq_kernel(const float* __restrict__ emb) {
    int t = blockIdx.x * blockDim.x + threadIdx.x;
    if (t == 0) g_paircnt = 0;
    if (t < NCB) g_rcnt[t] = 0;
    if (t >= NCB*MEMB) return;
    const float* row = emb + (size_t)t * DEMB;
    float acc = 0.f;
    #pragma unroll 8
    for (int d = 0; d < DEMB; d++) {
        float v = row[d];
        acc = __fadd_rn(acc, __fmul_rn(v, v));
    }
    g_esq[t] = acc;
    atomicMax(&g_esqmaxb[t >> 10], __float_as_int(acc));
}

// ---------------- x_sq (exact sequential) ----------------
__global__ void __launch_bounds__(256)
xsq_kernel(const float* __restrict__ x) {
    __shared__ float tile[8192];
    const int n = blockIdx.x & 7, b = blockIdx.x >> 3, tid = threadIdx.x;
    const size_t base = (size_t)b*65536 + (size_t)n*8192;
    for (int i = tid; i < 8192; i += 256) tile[i] = x[base + i];
    __syncthreads();
    if (tid < 64) {
        float acc = 0.f;
        #pragma unroll 8
        for (int d = 0; d < DEMB; d++) {
            float v = tile[d*64 + tid];
            acc = __fadd_rn(acc, __fmul_rn(v, v));
        }
        g_xsq[n*LPER + b*HLAT + tid] = acc;
    }
}

// ---------------- embedding -> swizzled fp16 (e*256) tiles, 64-code chunks ----------------
__global__ void bprep_kernel(const float* __restrict__ emb) {
    int u = blockIdx.x * blockDim.x + threadIdx.x;
    if (u >= NCB*MEMB*DEMB) return;
    float v = emb[u] * 256.0f;
    int d = u & 127, m = (u >> 7) & 1023, n = u >> 17;
    int row = m & 63, mc = m >> 6;
    int elem = ((n*16 + mc)*64 + row)*128 + (((d >> 3) ^ (row & 7)) << 3) + (d & 7);
    g_bh[elem] = __float2half_rn(v);
}

// ---------------- pass 1: fp16 1-MMA argmin, packed-key top-3, 3 CTAs/SM ----------------
// CTA = (n, batch row). 8 warps = 2(l) x 4(m); warp tile 32x16.
// m-chunks of 64 codes (16 iters), B double-buffered 2x16KB.
__global__ void __launch_bounds__(256, 3)
argmin_mma(const float* __restrict__ x) {
    extern __shared__ char sm[];
    const uint32_t sb = smem_u32(sm);
    __half* Ahi = (__half*)(sm);              // 16KB @0
    // B buffers: buf0 @16384 (16KB), buf1 @32768 (16KB)
    float* esq1_s = (float*)(sm + 49152);     // 4KB  (esq + 1.0)
    uint32_t* sk1 = (uint32_t*)(sm + 53248);  // 1KB
    uint32_t* sk2 = (uint32_t*)(sm + 54272);  // 1KB
    uint32_t* sk3 = (uint32_t*)(sm + 55296);  // 1KB

    const int n  = blockIdx.x >> 8;
    const int lt = blockIdx.x & 255;          // batch row b
    const int l0 = lt * 64;
    const int tid  = threadIdx.x;
    const int lane = tid & 31;
    const int w    = tid >> 5;
    const int wl   = w & 1;     // l half (32 rows)
    const int wm   = w >> 1;    // m quarter (16 cols of the 64-chunk)

    // prefetch B chunk 0
    {
        const char* src = (const char*)(g_bh + ((size_t)(n*16 + 0) << 13));
        uint32_t dst = sb + 16384;
        #pragma unroll
        for (int i = 0; i < 4; i++)
            cp16(dst + (tid + i*256)*16, src + (tid + i*256)*16);
        CP_COMMIT();
    }

    // stage esq+1
    for (int i = tid; i < 1024; i += 256) esq1_s[i] = g_esq[n*1024 + i] + 1.0f;

    // stage A tile fp16 (swizzled): rows j = h (0..63), cols d
    for (int idx = tid; idx < 8192; idx += 256) {
        int d = idx >> 6, j = idx & 63;
        float v = x[(size_t)lt*65536 + (size_t)n*8192 + d*64 + j];
        int elem = j*128 + (((d >> 3) ^ (j & 7)) << 3) + (d & 7);
        Ahi[elem] = __float2half_rn(v);
    }

    // ldmatrix addresses
    const uint32_t sAh = sb, sBh0 = sb + 16384;
    const int q  = lane >> 3;
    const int r8 = lane & 7;
    const int cqA = q >> 1;
    const int cqB = q & 1;
    uint32_t aBase[2]; int a7[2];
    #pragma unroll
    for (int t2 = 0; t2 < 2; t2++) {
        int rowA = wl*32 + t2*16 + r8 + (q & 1)*8;
        aBase[t2] = sAh + rowA*256; a7[t2] = rowA & 7;
    }
    uint32_t bBase; int b7;
    {
        int rowB = wm*16 + r8 + (q >> 1)*8;
        bBase = sBh0 + rowB*256; b7 = rowB & 7;
    }

    // packed-key top-3 per slot: slots = (t2, row-half)
    uint32_t K1[4], K2[4], K3[4];
    #pragma unroll
    for (int s = 0; s < 4; s++) { K1[s] = 0xFFFFFFFFu; K2[s] = 0xFFFFFFFFu; K3[s] = 0xFFFFFFFFu; }

    const int col2 = (lane & 3) * 2;

#define LAD(s, k) { \
    uint32_t b_ = max(K1[s], (k)); K1[s] = min(K1[s], (k)); \
    uint32_t c_ = max(K2[s], b_);  K2[s] = min(K2[s], b_); \
    K3[s] = min(K3[s], c_); }

    for (int mc = 0; mc < 16; mc++) {
        if (mc < 15) {
            const char* src = (const char*)(g_bh + ((size_t)(n*16 + mc + 1) << 13));
            uint32_t dbuf = sb + 16384 + (uint32_t)(((mc + 1) & 1) * 16384);
            #pragma unroll
            for (int i = 0; i < 4; i++)
                cp16(dbuf + (tid + i*256)*16, src + (tid + i*256)*16);
            CP_COMMIT();
            CP_WAIT(1);
        } else {
            CP_WAIT(0);
        }
        __syncthreads();

        const uint32_t bufOff = (uint32_t)((mc & 1) * 16384);

        float acc[2][2][4];
        #pragma unroll
        for (int t2 = 0; t2 < 2; t2++)
            #pragma unroll
            for (int mt = 0; mt < 2; mt++)
                #pragma unroll
                for (int c = 0; c < 4; c++) acc[t2][mt][c] = 0.f;

        #pragma unroll
        for (int ks = 0; ks < 8; ks++) {
            const int ks2 = ks * 2;
            uint32_t ah[2][4];
            #pragma unroll
            for (int t2 = 0; t2 < 2; t2++) {
                uint32_t off = (uint32_t)(((ks2 + cqA) ^ a7[t2]) << 4);
                ldsm4(ah[t2], aBase[t2] + off);
            }
            uint32_t bh[4];
            {
                uint32_t off = (uint32_t)(((ks2 + cqB) ^ b7) << 4) + bufOff;
                ldsm4(bh, bBase + off);
            }
            #pragma unroll
            for (int t2 = 0; t2 < 2; t2++) {
                mma_f16(acc[t2][0], ah[t2], &bh[0]);
                mma_f16(acc[t2][1], ah[t2], &bh[2]);
            }
        }

        // epilogue: t' = (esq+1) - acc/128 ; packed key = (bits & ~1023) | m
        const int mbase = mc*64 + wm*16;
        #pragma unroll
        for (int mt = 0; mt < 2; mt++) {
            float e0 = esq1_s[mbase + mt*8 + col2];
            float e1 = esq1_s[mbase + mt*8 + col2 + 1];
            uint32_t mm0 = (uint32_t)(mbase + mt*8 + col2);
            #pragma unroll
            for (int t2 = 0; t2 < 2; t2++) {
                float ta = fmaf(acc[t2][mt][0], -0.0078125f, e0);
                float tb = fmaf(acc[t2][mt][1], -0.0078125f, e1);
                uint32_t ka = (__float_as_uint(ta) & 0xFFFFFC00u) | mm0;
                uint32_t kb = (__float_as_uint(tb) & 0xFFFFFC00u) | (mm0 + 1u);
                LAD(t2*2, ka); LAD(t2*2, kb);
                float tc = fmaf(acc[t2][mt][2], -0.0078125f, e0);
                float td = fmaf(acc[t2][mt][3], -0.0078125f, e1);
                uint32_t kc = (__float_as_uint(tc) & 0xFFFFFC00u) | mm0;
                uint32_t kd = (__float_as_uint(td) & 0xFFFFFC00u) | (mm0 + 1u);
                LAD(t2*2 + 1, kc); LAD(t2*2 + 1, kd);
            }
        }
        __syncthreads();
    }
#undef LAD

    // quad reduce (lanes sharing lane>>2 hold the same rows)
    #pragma unroll
    for (int s = 0; s < 4; s++) {
        #pragma unroll
        for (int off = 1; off <= 2; off <<= 1) {
            uint32_t o1 = __shfl_xor_sync(0xffffffffu, K1[s], off);
            uint32_t o2 = __shfl_xor_sync(0xffffffffu, K2[s], off);
            uint32_t o3 = __shfl_xor_sync(0xffffffffu, K3[s], off);
            kmrg(K1[s], K2[s], K3[s], o1, o2, o3);
        }
    }
    if ((lane & 3) == 0) {
        const int g = lane >> 2;
        #pragma unroll
        for (int s = 0; s < 4; s++) {
            int row = wl*32 + (s >> 1)*16 + g + (s & 1)*8;
            sk1[wm*64 + row] = K1[s];
            sk2[wm*64 + row] = K2[s];
            sk3[wm*64 + row] = K3[s];
        }
    }
    __syncthreads();

    if (tid < 64) {
        uint32_t k1 = sk1[tid], k2 = sk2[tid], k3 = sk3[tid];
        #pragma unroll
        for (int qq = 1; qq < 4; qq++)
            kmrg(k1, k2, k3, sk1[qq*64 + tid], sk2[qq*64 + tid], sk3[qq*64 + tid]);

        int i1 = (int)(k1 & 1023u), i2 = (int)(k2 & 1023u);
        float b1f = __uint_as_float(k1 & 0xFFFFFC00u);
        float b2f = __uint_as_float(k2 & 0xFFFFFC00u);
        float b3f = __uint_as_float(k3 & 0xFFFFFC00u);

        int l = l0 + tid;
        int id = n*LPER + l;
        g_indices[id] = i1;
        // margin: 2^-8*sqrt(xsq*esqmax) + slack (fp16 rounding + key truncation)
        float mar = 0.00390625f * sqrtf(g_xsq[id] * __int_as_float(g_esqmaxb[n])) + 5.0e-4f;
        if (b2f - b1f < mar) {
            if (b3f - b1f < mar) {
                g_fixkey[id] = 0xFFFFFFFFFFFFFFFFull;
                int p = atomicAdd(&g_rcnt[n], 1);
                g_rlist[n*LPER + p] = l;
            } else {
                int p = atomicAdd(&g_paircnt, 1);
                g_pairlist[p] = make_int2((n << 14) | l, i1 | (i2 << 16));
            }
        }
    }
}

// ---------------- pack pair x rows ----------------
__global__ void __launch_bounds__(128)
packP_kernel(const float* __restrict__ x) {
    const int cnt = g_paircnt;
    for (int u = blockIdx.x; u < cnt; u += gridDim.x) {
        int nl = g_pairlist[u].x;
        int n = nl >> 14, l = nl & 16383;
        int b = l >> 6, h = l & 63;
        g_xpp[(size_t)u*128 + threadIdx.x] =
            x[(size_t)b*65536 + (size_t)n*8192 + threadIdx.x*64 + h];
    }
}

// ---------------- pack rescan x rows ----------------
__global__ void __launch_bounds__(128)
packR_kernel(const float* __restrict__ x) {
    const int n = blockIdx.y;
    const int cnt = g_rcnt[n];
    for (int p = blockIdx.x; p < cnt; p += gridDim.x) {
        int l = g_rlist[n*LPER + p];
        int b = l >> 6, h = l & 63;
        g_xpr[((size_t)n*LPER + p)*128 + threadIdx.x] =
            x[(size_t)b*65536 + (size_t)n*8192 + threadIdx.x*64 + h];
    }
}

// ---------------- pass 2a: exact pairwise compare ----------------
__global__ void __launch_bounds__(256)
pairfix_kernel(const float* __restrict__ emb) {
    extern __shared__ float xsf[];            // [128 entries][stride 132]
    __shared__ float Dv[256];
    __shared__ int2  ent[128];
    const int tid = threadIdx.x;
    const int cnt = g_paircnt;

    for (int base = blockIdx.x*128; base < cnt; base += gridDim.x*128) {
        int nent = cnt - base; if (nent > 128) nent = 128;
        if (tid < nent) ent[tid] = g_pairlist[base + tid];
        __syncthreads();
        for (int i = tid; i < nent*32; i += 256) {
            int e = i >> 5, qv = (i & 31) * 4;
            float4 v = *(const float4*)&g_xpp[(size_t)(base + e)*128 + qv];
            float* dst = &xsf[e*132 + qv];
            dst[0] = v.x; dst[1] = v.y; dst[2] = v.z; dst[3] = v.w;
        }
        __syncthreads();
        if ((tid >> 1) < nent) {
            int e = tid >> 1, c = tid & 1;
            int nl = ent[e].x; int n = nl >> 14, l = nl & 16383;
            int m = c ? (ent[e].y >> 16) : (ent[e].y & 0xffff);
            const float4* er4 = (const float4*)(emb + ((size_t)n*1024 + m)*128);
            const float* xr = &xsf[e*132];
            float cc = 0.f;
            #pragma unroll 8
            for (int qq = 0; qq < 32; qq++) {
                float4 e4 = er4[qq];
                cc = fmaf(xr[qq*4+0], e4.x, cc);
                cc = fmaf(xr[qq*4+1], e4.y, cc);
                cc = fmaf(xr[qq*4+2], e4.z, cc);
                cc = fmaf(xr[qq*4+3], e4.w, cc);
            }
            Dv[tid] = __fsub_rn(__fadd_rn(g_esq[n*1024 + m], g_xsq[n*LPER + l]), 2.f*cc);
        }
        __syncthreads();
        if (tid < nent) {
            int m0 = ent[tid].y & 0xffff, m1 = ent[tid].y >> 16;
            float D0 = Dv[2*tid], D1 = Dv[2*tid + 1];
            int win;
            if (D0 < D1) win = m0;
            else if (D1 < D0) win = m1;
            else win = (m0 < m1) ? m0 : m1;
            int nl = ent[tid].x;
            g_indices[(nl >> 14)*LPER + (nl & 16383)] = win;
        }
        __syncthreads();
    }
}

// ---------------- pass 2b: full exact rescan, E staged in smem ----------------
__global__ void __launch_bounds__(128)
rescan_kernel(const float* __restrict__ emb) {
    extern __shared__ float fsm[];
    float* E     = fsm;                       // [128 codes][stride 132]
    float* xs    = fsm + 128*132;             // [8 rows][128]
    float* esq_c = xs + 1024;                 // [128]
    float* xsq_s = esq_c + 128;               // [8]
    unsigned long long* wred = (unsigned long long*)(xsq_s + 8);   // [4][8]

    const int n     = blockIdx.x >> 7;
    const int mc    = (blockIdx.x >> 4) & 7;
    const int slice = blockIdx.x & 15;
    const int tid   = threadIdx.x;
    const int wid   = tid >> 5, lane = tid & 31;

    const int cnt = g_rcnt[n];
    if (cnt == 0) return;

    const float* src = emb + ((size_t)n*1024 + mc*128)*128;
    for (int i = tid; i < 16384; i += 128) {
        int r = i >> 7, d = i & 127;
        E[r*132 + d] = src[i];
    }
    esq_c[tid] = g_esq[n*1024 + mc*128 + tid];
    __syncthreads();

    const unsigned code_m = (unsigned)(mc*128 + tid);

    for (int g0 = slice*8; g0 < cnt; g0 += 16*8) {
        #pragma unroll
        for (int r = 0; r < 8; r++) {
            int u = g0 + r;
            int uc = (u < cnt) ? u : (cnt - 1);
            xs[r*128 + tid] = g_xpr[((size_t)n*LPER + uc)*128 + tid];
        }
        if (tid < 8) {
            int u = g0 + tid;
            int uc = (u < cnt) ? u : (cnt - 1);
            xsq_s[tid] = g_xsq[n*LPER + g_rlist[n*LPER + uc]];
        }
        __syncthreads();

        float c[8];
        #pragma unroll
        for (int r = 0; r < 8; r++) c[r] = 0.f;
        const float4* er4 = (const float4*)&E[tid*132];
        #pragma unroll 8
        for (int qq = 0; qq < 32; qq++) {
            float4 e = er4[qq];
            #pragma unroll
            for (int r = 0; r < 8; r++) {
                float4 xr = *(const float4*)&xs[r*128 + qq*4];
                c[r] = fmaf(xr.x, e.x, c[r]);
                c[r] = fmaf(xr.y, e.y, c[r]);
                c[r] = fmaf(xr.z, e.z, c[r]);
                c[r] = fmaf(xr.w, e.w, c[r]);
            }
        }

        #pragma unroll
        for (int r = 0; r < 8; r++) {
            float D = __fsub_rn(__fadd_rn(esq_c[tid], xsq_s[r]), 2.f*c[r]);
            unsigned ud = __float_as_uint(D);
            ud = (ud & 0x80000000u) ? ~ud : (ud | 0x80000000u);
            unsigned long long key = ((unsigned long long)ud << 32) | code_m;
            #pragma unroll
            for (int o = 16; o; o >>= 1) {
                unsigned long long ok = __shfl_xor_sync(0xffffffffu, key, o);
                if (ok < key) key = ok;
            }
            if (lane == 0) wred[wid*8 + r] = key;
        }
        __syncthreads();
        if (tid < 8) {
            int u = g0 + tid;
            if (u < cnt) {
                unsigned long long k = wred[tid];
                if (wred[8  + tid] < k) k = wred[8  + tid];
                if (wred[16 + tid] < k) k = wred[16 + tid];
                if (wred[24 + tid] < k) k = wred[24 + tid];
                int l = g_rlist[n*LPER + u];
                atomicMin(&g_fixkey[n*LPER + l], k);
            }
        }
        __syncthreads();
    }
}

// ---------------- unpack rescan indices ----------------
__global__ void unpack_kernel() {
    const int n = blockIdx.x;
    const int cnt = g_rcnt[n];
    for (int p = threadIdx.x; p < cnt; p += blockDim.x) {
        int l = g_rlist[n*LPER + p];
        int id = n*LPER + l;
        g_indices[id] = (int)(unsigned)(g_fixkey[id] & 0xFFFFFFFFull);
    }
}

// ---------------- gather + z_q + loss partials + indices out (float4) ----------------
__global__ void __launch_bounds__(256)
gather_kernel(const float* __restrict__ x, const float* __restrict__ emb,
              float* __restrict__ out, float* __restrict__ out_idx, int write_extras) {
    __shared__ int   midx[64];
    __shared__ float rows[64*129];
    __shared__ float red[256];
    const int n = blockIdx.x & 7, b = blockIdx.x >> 3, tid = threadIdx.x;

    if (tid < 64) {
        int m = g_indices[n*LPER + b*HLAT + tid];
        midx[tid] = m;
        if (write_extras) out_idx[b*(NCB*HLAT) + n*HLAT + tid] = (float)m;
    }
    __syncthreads();
    for (int idx = tid; idx < 64*32; idx += 256) {
        int r = idx >> 5, dq = (idx & 31) * 4;
        float4 v = *(const float4*)&emb[((size_t)n*MEMB + midx[r])*DEMB + dq];
        float* dst = &rows[r*129 + dq];
        dst[0] = v.x; dst[1] = v.y; dst[2] = v.z; dst[3] = v.w;
    }
    __syncthreads();
    float s = 0.f;
    const size_t base = (size_t)b*65536 + (size_t)n*8192;
    for (int idx4 = tid; idx4 < 2048; idx4 += 256) {
        int d = idx4 >> 4, h4 = (idx4 & 15) * 4;
        float4 q;
        q.x = rows[(h4+0)*129 + d];
        q.y = rows[(h4+1)*129 + d];
        q.z = rows[(h4+2)*129 + d];
        q.w = rows[(h4+3)*129 + d];
        float4 xv = *(const float4*)&x[base + d*64 + h4];
        *(float4*)&out[base + d*64 + h4] = q;
        float dx = xv.x - q.x, dy = xv.y - q.y, dz = xv.z - q.z, dw = xv.w - q.w;
        s += dx*dx + dy*dy + dz*dz + dw*dw;
    }
    red[tid] = s;
    __syncthreads();
    for (int st = 128; st; st >>= 1) { if (tid < st) red[tid] += red[tid+st]; __syncthreads(); }
    if (tid == 0) g_part[blockIdx.x] = red[0];
}

// ---------------- entropy ----------------
__global__ void entropy_kernel() {
    __shared__ int   hist[MEMB];
    __shared__ float red[256];
    const int n = blockIdx.x, tid = threadIdx.x;
    for (int i = tid; i < MEMB; i += 256) hist[i] = 0;
    __syncthreads();
    for (int l = tid; l < LPER; l += 256) atomicAdd(&hist[g_indices[n*LPER + l]], 1);
    __syncthreads();
    float s = 0.f;
    for (int m = tid; m < MEMB; m += 256) {
        float p = (float)hist[m] * (1.f / (float)LPER);
        s += p * logf(p + 1e-10f);
    }
    red[tid] = s;
    __syncthreads();
    for (int st = 128; st; st >>= 1) { if (tid < st) red[tid] += red[tid+st]; __syncthreads(); }
    if (tid == 0) g_ent[n] = -red[0];
}

// ---------------- finalize ----------------
__global__ void finalize_kernel(float* __restrict__ out, int write_scalars) {
    __shared__ float red[256];
    const int tid = threadIdx.x;
    float s = 0.f;
    for (int i = tid; i < 2048; i += 256) s += g_part[i];
    red[tid] = s;
    __syncthreads();
    for (int st = 128; st; st >>= 1) { if (tid < st) red[tid] += red[tid+st]; __syncthreads(); }
    if (tid == 0 && write_scalars) {
        float loss = 0.25f * red[0] / (float)ZQ_ELEMS;
        float ent = 0.f, perp = 0.f;
        #pragma unroll
        for (int n = 0; n < NCB; n++) { ent += g_ent[n]; perp += expf(g_ent[n]); }
        out[ZQ_ELEMS + 0] = loss;
        out[ZQ_ELEMS + 1] = ent * (1.f / NCB);
        out[ZQ_ELEMS + 2] = perp * (1.f / NCB);
    }
}

// ---------------- launch ----------------
extern "C" void kernel_launch(void* const* d_in, const int* in_sizes, int n_in,
                              void* d_out, int out_size) {
    const float* x   = (const float*)d_in[0];
    const float* emb = (const float*)d_in[1];
    if (n_in >= 2 && in_sizes[0] == NCB*MEMB*DEMB && in_sizes[1] == ZQ_ELEMS) {
        const float* t = x; x = emb; emb = t;
    }
    float* out = (float*)d_out;
    const int full = (out_size >= ZQ_ELEMS + 3 + IDX_ELEMS) ? 1 : 0;

    const int SMEM_ARG = 56320;
    cudaFuncSetAttribute(argmin_mma, cudaFuncAttributeMaxDynamicSharedMemorySize, SMEM_ARG);
    const int SMEM_PAIR = 128*132*4;
    cudaFuncSetAttribute(pairfix_kernel, cudaFuncAttributeMaxDynamicSharedMemorySize, SMEM_PAIR);
    const int SMEM_RES = (128*132 + 8*128 + 128 + 8) * 4 + 32 * 8;
    cudaFuncSetAttribute(rescan_kernel, cudaFuncAttributeMaxDynamicSharedMemorySize, SMEM_RES);

    esq_kernel<<<(NCB*MEMB + 255)/256, 256>>>(emb);
    xsq_kernel<<<BATCH*NCB, 256>>>(x);
    bprep_kernel<<<(NCB*MEMB*DEMB + 255)/256, 256>>>(emb);
    argmin_mma<<<NCB * (LPER/64), 256, SMEM_ARG>>>(x);
    packP_kernel<<<2048, 128>>>(x);
    packR_kernel<<<dim3(256, NCB), 128>>>(x);
    pairfix_kernel<<<296, 256, SMEM_PAIR>>>(emb);
    rescan_kernel<<<NCB*8*16, 128, SMEM_RES>>>(emb);
    unpack_kernel<<<NCB, 256>>>();
    gather_kernel<<<BATCH*NCB, 256>>>(x, emb, out, out + ZQ_ELEMS + 3, full);
    entropy_kernel<<<NCB, 256>>>();
    finalize_kernel<<<1, 256>>>(out, full);
}

// round 15
// speedup vs baseline: 2.9180x; 1.0245x over previous
#include <cuda_runtime.h>
#include <cuda_fp16.h>
#include <math.h>
#include <stdint.h>

#define NCB   8
#define MEMB  1024
#define DEMB  128
#define HLAT  64
#define BATCH 256
#define LPER  (BATCH*HLAT)              /* 16384 per codebook */
#define ZQ_ELEMS (BATCH*NCB*DEMB*HLAT)  /* 16777216 */
#define IDX_ELEMS (BATCH*NCB*HLAT)      /* 131072 */

// ---------------- device scratch ----------------
__device__ int   g_indices[NCB*LPER];
__device__ float g_esq[NCB*MEMB];
__device__ int   g_esqmaxb[NCB];
__device__ float g_xsq[NCB*LPER];
__device__ float g_part[2048];
__device__ float g_ent[NCB];
__device__ int   g_paircnt;
__device__ int2  g_pairlist[NCB*LPER];        // .x=(n<<14)|l, .y=i1|(i2<<16)
__device__ float g_xpp[(size_t)NCB*LPER*DEMB]; // packed x rows for pair entries
__device__ int   g_rcnt[NCB];
__device__ int   g_rlist[NCB*LPER];
__device__ float g_xpr[(size_t)NCB*LPER*DEMB];
__device__ unsigned long long g_fixkey[NCB*LPER];
// pre-swizzled fp16 embedding tiles (e*256): [n][mchunk 16][row 64][k 128]
__device__ __half g_bh[NCB*MEMB*DEMB];

// ---------------- PTX helpers ----------------
__device__ __forceinline__ uint32_t smem_u32(const void* p) {
    uint32_t a;
    asm("{ .reg .u64 t; cvta.to.shared.u64 t, %1; cvt.u32.u64 %0, t; }" : "=r"(a) : "l"(p));
    return a;
}
__device__ __forceinline__ void ldsm4(uint32_t* r, uint32_t addr) {
    asm volatile("ldmatrix.sync.aligned.m8n8.x4.shared.b16 {%0,%1,%2,%3}, [%4];"
        : "=r"(r[0]), "=r"(r[1]), "=r"(r[2]), "=r"(r[3]) : "r"(addr));
}
__device__ __forceinline__ void mma_f16(float* c, const uint32_t* a, const uint32_t* b) {
    asm volatile("mma.sync.aligned.m16n8k16.row.col.f32.f16.f16.f32 "
        "{%0,%1,%2,%3}, {%4,%5,%6,%7}, {%8,%9}, {%0,%1,%2,%3};"
        : "+f"(c[0]), "+f"(c[1]), "+f"(c[2]), "+f"(c[3])
        : "r"(a[0]), "r"(a[1]), "r"(a[2]), "r"(a[3]), "r"(b[0]), "r"(b[1]));
}
__device__ __forceinline__ void cp16(uint32_t dst, const void* src) {
    asm volatile("cp.async.cg.shared.global [%0], [%1], 16;" :: "r"(dst), "l"(src) : "memory");
}
#define CP_COMMIT() asm volatile("cp.async.commit_group;" ::: "memory")
#define CP_WAIT(n)  asm volatile("cp.async.wait_group %0;" :: "n"(n) : "memory")

// merge two sorted uint triples (7 min/max ops)
__device__ __forceinline__ void kmrg(uint32_t& a1, uint32_t& a2, uint32_t& a3,
                                     uint32_t b1, uint32_t b2, uint32_t b3) {
    uint32_t M  = max(a1, b1);
    uint32_t m2 = min(a2, b2);
    uint32_t r1 = min(a1, b1);
    uint32_t r2 = min(M, m2);
    uint32_t r3 = min(min(a3, b3), max(m2, M));
    a1 = r1; a2 = r2; a3 = r3;
}

// ---------------- e_sq (exact sequential) + per-n max + counter reset ----------------
__global__ void esq_kernel(const float* __restrict__ emb) {
    int t = blockIdx.x * blockDim.x + threadIdx.x;
    if (t == 0) g_paircnt = 0;
    if (t < NCB) g_rcnt[t] = 0;
    if (t >= NCB*MEMB) return;
    const float* row = emb + (size_t)t * DEMB;
    float acc = 0.f;
    #pragma unroll 8
    for (int d = 0; d < DEMB; d++) {
        float v = row[d];
        acc = __fadd_rn(acc, __fmul_rn(v, v));
    }
    g_esq[t] = acc;
    atomicMax(&g_esqmaxb[t >> 10], __float_as_int(acc));
}

// ---------------- x_sq (exact sequential) ----------------
__global__ void __launch_bounds__(256)
xsq_kernel(const float* __restrict__ x) {
    __shared__ float tile[8192];
    const int n = blockIdx.x & 7, b = blockIdx.x >> 3, tid = threadIdx.x;
    const size_t base = (size_t)b*65536 + (size_t)n*8192;
    for (int i = tid; i < 8192; i += 256) tile[i] = x[base + i];
    __syncthreads();
    if (tid < 64) {
        float acc = 0.f;
        #pragma unroll 8
        for (int d = 0; d < DEMB; d++) {
            float v = tile[d*64 + tid];
            acc = __fadd_rn(acc, __fmul_rn(v, v));
        }
        g_xsq[n*LPER + b*HLAT + tid] = acc;
    }
}

// ---------------- embedding -> swizzled fp16 (e*256) tiles, 64-code chunks ----------------
__global__ void bprep_kernel(const float* __restrict__ emb) {
    int u = blockIdx.x * blockDim.x + threadIdx.x;
    if (u >= NCB*MEMB*DEMB) return;
    float v = emb[u] * 256.0f;
    int d = u & 127, m = (u >> 7) & 1023, n = u >> 17;
    int row = m & 63, mc = m >> 6;
    int elem = ((n*16 + mc)*64 + row)*128 + (((d >> 3) ^ (row & 7)) << 3) + (d & 7);
    g_bh[elem] = __float2half_rn(v);
}

// ---------------- pass 1: fp16 1-MMA argmin, A fragments in registers ----------------
// CTA = (n, batch row). 8 warps = 2(l) x 4(m); warp tile 32x16.
// A frags hoisted to regs (64 regs); loop does B-only ldsm. 2 CTAs/SM.
__global__ void __launch_bounds__(256, 2)
argmin_mma(const float* __restrict__ x) {
    extern __shared__ char sm[];
    const uint32_t sb = smem_u32(sm);
    // B buffers: buf0 @0 (16KB), buf1 @16384 (16KB)
    __half* Ast = (__half*)(sm + 32768);      // A staging 16KB
    float* esq1_s = (float*)(sm + 49152);     // 4KB  (esq + 1.0)
    uint32_t* sk1 = (uint32_t*)(sm + 53248);  // 1KB
    uint32_t* sk2 = (uint32_t*)(sm + 54272);  // 1KB
    uint32_t* sk3 = (uint32_t*)(sm + 55296);  // 1KB

    const int n  = blockIdx.x >> 8;
    const int lt = blockIdx.x & 255;          // batch row b
    const int l0 = lt * 64;
    const int tid  = threadIdx.x;
    const int lane = tid & 31;
    const int w    = tid >> 5;
    const int wl   = w & 1;     // l half (32 rows)
    const int wm   = w >> 1;    // m quarter (16 cols of the 64-chunk)

    // prefetch B chunk 0 -> buf0
    {
        const char* src = (const char*)(g_bh + ((size_t)(n*16 + 0) << 13));
        #pragma unroll
        for (int i = 0; i < 4; i++)
            cp16(sb + (tid + i*256)*16, src + (tid + i*256)*16);
        CP_COMMIT();
    }

    // stage esq+1
    for (int i = tid; i < 1024; i += 256) esq1_s[i] = g_esq[n*1024 + i] + 1.0f;

    // stage A tile fp16 (swizzled): rows j = h (0..63), cols d
    for (int idx = tid; idx < 8192; idx += 256) {
        int d = idx >> 6, j = idx & 63;
        float v = x[(size_t)lt*65536 + (size_t)n*8192 + d*64 + j];
        int elem = j*128 + (((d >> 3) ^ (j & 7)) << 3) + (d & 7);
        Ast[elem] = __float2half_rn(v);
    }
    __syncthreads();   // A staging visible

    // per-lane addressing
    const int q  = lane >> 3;
    const int r8 = lane & 7;
    const int cqA = q >> 1;
    const int cqB = q & 1;

    // hoist A fragments into registers: ah[ks*2+t2][4]
    uint32_t ah[16][4];
    {
        #pragma unroll
        for (int t2 = 0; t2 < 2; t2++) {
            int rowA = wl*32 + t2*16 + r8 + (q & 1)*8;
            uint32_t aBase = sb + 32768u + (uint32_t)rowA*256u;
            int a7 = rowA & 7;
            #pragma unroll
            for (int ks = 0; ks < 8; ks++) {
                uint32_t off = (uint32_t)(((ks*2 + cqA) ^ a7) << 4);
                ldsm4(ah[ks*2 + t2], aBase + off);
            }
        }
    }

    uint32_t bBase; int b7;
    {
        int rowB = wm*16 + r8 + (q >> 1)*8;
        bBase = sb + (uint32_t)rowB*256u; b7 = rowB & 7;
    }

    // packed-key top-3 per slot: slots = (t2, row-half)
    uint32_t K1[4], K2[4], K3[4];
    #pragma unroll
    for (int s = 0; s < 4; s++) { K1[s] = 0xFFFFFFFFu; K2[s] = 0xFFFFFFFFu; K3[s] = 0xFFFFFFFFu; }

    const int col2 = (lane & 3) * 2;

#define LAD(s, k) { \
    uint32_t b_ = max(K1[s], (k)); K1[s] = min(K1[s], (k)); \
    uint32_t c_ = max(K2[s], b_);  K2[s] = min(K2[s], b_); \
    K3[s] = min(K3[s], c_); }

    for (int mc = 0; mc < 16; mc++) {
        if (mc < 15) {
            const char* src = (const char*)(g_bh + ((size_t)(n*16 + mc + 1) << 13));
            uint32_t dbuf = sb + (uint32_t)(((mc + 1) & 1) * 16384);
            #pragma unroll
            for (int i = 0; i < 4; i++)
                cp16(dbuf + (tid + i*256)*16, src + (tid + i*256)*16);
            CP_COMMIT();
            CP_WAIT(1);
        } else {
            CP_WAIT(0);
        }
        __syncthreads();

        const uint32_t bufOff = (uint32_t)((mc & 1) * 16384);

        float acc[2][2][4];
        #pragma unroll
        for (int t2 = 0; t2 < 2; t2++)
            #pragma unroll
            for (int mt = 0; mt < 2; mt++)
                #pragma unroll
                for (int c = 0; c < 4; c++) acc[t2][mt][c] = 0.f;

        #pragma unroll
        for (int ks = 0; ks < 8; ks++) {
            uint32_t bh[4];
            {
                uint32_t off = (uint32_t)(((ks*2 + cqB) ^ b7) << 4) + bufOff;
                ldsm4(bh, bBase + off);
            }
            #pragma unroll
            for (int t2 = 0; t2 < 2; t2++) {
                mma_f16(acc[t2][0], ah[ks*2 + t2], &bh[0]);
                mma_f16(acc[t2][1], ah[ks*2 + t2], &bh[2]);
            }
        }

        // epilogue: t' = (esq+1) - acc/128 ; packed key = (bits & ~1023) | m
        const int mbase = mc*64 + wm*16;
        #pragma unroll
        for (int mt = 0; mt < 2; mt++) {
            float e0 = esq1_s[mbase + mt*8 + col2];
            float e1 = esq1_s[mbase + mt*8 + col2 + 1];
            uint32_t mm0 = (uint32_t)(mbase + mt*8 + col2);
            #pragma unroll
            for (int t2 = 0; t2 < 2; t2++) {
                float ta = fmaf(acc[t2][mt][0], -0.0078125f, e0);
                float tb = fmaf(acc[t2][mt][1], -0.0078125f, e1);
                uint32_t ka = (__float_as_uint(ta) & 0xFFFFFC00u) | mm0;
                uint32_t kb = (__float_as_uint(tb) & 0xFFFFFC00u) | (mm0 + 1u);
                LAD(t2*2, ka); LAD(t2*2, kb);
                float tc = fmaf(acc[t2][mt][2], -0.0078125f, e0);
                float td = fmaf(acc[t2][mt][3], -0.0078125f, e1);
                uint32_t kc = (__float_as_uint(tc) & 0xFFFFFC00u) | mm0;
                uint32_t kd = (__float_as_uint(td) & 0xFFFFFC00u) | (mm0 + 1u);
                LAD(t2*2 + 1, kc); LAD(t2*2 + 1, kd);
            }
        }
        __syncthreads();   // all warps done reading this buffer before overwrite
    }
#undef LAD

    // quad reduce (lanes sharing lane>>2 hold the same rows)
    #pragma unroll
    for (int s = 0; s < 4; s++) {
        #pragma unroll
        for (int off = 1; off <= 2; off <<= 1) {
            uint32_t o1 = __shfl_xor_sync(0xffffffffu, K1[s], off);
            uint32_t o2 = __shfl_xor_sync(0xffffffffu, K2[s], off);
            uint32_t o3 = __shfl_xor_sync(0xffffffffu, K3[s], off);
            kmrg(K1[s], K2[s], K3[s], o1, o2, o3);
        }
    }
    if ((lane & 3) == 0) {
        const int g = lane >> 2;
        #pragma unroll
        for (int s = 0; s < 4; s++) {
            int row = wl*32 + (s >> 1)*16 + g + (s & 1)*8;
            sk1[wm*64 + row] = K1[s];
            sk2[wm*64 + row] = K2[s];
            sk3[wm*64 + row] = K3[s];
        }
    }
    __syncthreads();

    if (tid < 64) {
        uint32_t k1 = sk1[tid], k2 = sk2[tid], k3 = sk3[tid];
        #pragma unroll
        for (int qq = 1; qq < 4; qq++)
            kmrg(k1, k2, k3, sk1[qq*64 + tid], sk2[qq*64 + tid], sk3[qq*64 + tid]);

        int i1 = (int)(k1 & 1023u), i2 = (int)(k2 & 1023u);
        float b1f = __uint_as_float(k1 & 0xFFFFFC00u);
        float b2f = __uint_as_float(k2 & 0xFFFFFC00u);
        float b3f = __uint_as_float(k3 & 0xFFFFFC00u);

        int l = l0 + tid;
        int id = n*LPER + l;
        g_indices[id] = i1;
        float mar = 0.00390625f * sqrtf(g_xsq[id] * __int_as_float(g_esqmaxb[n])) + 5.0e-4f;
        if (b2f - b1f < mar) {
            if (b3f - b1f < mar) {
                g_fixkey[id] = 0xFFFFFFFFFFFFFFFFull;
                int p = atomicAdd(&g_rcnt[n], 1);
                g_rlist[n*LPER + p] = l;
            } else {
                int p = atomicAdd(&g_paircnt, 1);
                g_pairlist[p] = make_int2((n << 14) | l, i1 | (i2 << 16));
            }
        }
    }
}

// ---------------- pack pair x rows ----------------
__global__ void __launch_bounds__(128)
packP_kernel(const float* __restrict__ x) {
    const int cnt = g_paircnt;
    for (int u = blockIdx.x; u < cnt; u += gridDim.x) {
        int nl = g_pairlist[u].x;
        int n = nl >> 14, l = nl & 16383;
        int b = l >> 6, h = l & 63;
        g_xpp[(size_t)u*128 + threadIdx.x] =
            x[(size_t)b*65536 + (size_t)n*8192 + threadIdx.x*64 + h];
    }
}

// ---------------- pack rescan x rows ----------------
__global__ void __launch_bounds__(128)
packR_kernel(const float* __restrict__ x) {
    const int n = blockIdx.y;
    const int cnt = g_rcnt[n];
    for (int p = blockIdx.x; p < cnt; p += gridDim.x) {
        int l = g_rlist[n*LPER + p];
        int b = l >> 6, h = l & 63;
        g_xpr[((size_t)n*LPER + p)*128 + threadIdx.x] =
            x[(size_t)b*65536 + (size_t)n*8192 + threadIdx.x*64 + h];
    }
}

// ---------------- pass 2a: exact pairwise compare ----------------
__global__ void __launch_bounds__(256)
pairfix_kernel(const float* __restrict__ emb) {
    extern __shared__ float xsf[];            // [128 entries][stride 132]
    __shared__ float Dv[256];
    __shared__ int2  ent[128];
    const int tid = threadIdx.x;
    const int cnt = g_paircnt;

    for (int base = blockIdx.x*128; base < cnt; base += gridDim.x*128) {
        int nent = cnt - base; if (nent > 128) nent = 128;
        if (tid < nent) ent[tid] = g_pairlist[base + tid];
        __syncthreads();
        for (int i = tid; i < nent*32; i += 256) {
            int e = i >> 5, qv = (i & 31) * 4;
            float4 v = *(const float4*)&g_xpp[(size_t)(base + e)*128 + qv];
            float* dst = &xsf[e*132 + qv];
            dst[0] = v.x; dst[1] = v.y; dst[2] = v.z; dst[3] = v.w;
        }
        __syncthreads();
        if ((tid >> 1) < nent) {
            int e = tid >> 1, c = tid & 1;
            int nl = ent[e].x; int n = nl >> 14, l = nl & 16383;
            int m = c ? (ent[e].y >> 16) : (ent[e].y & 0xffff);
            const float4* er4 = (const float4*)(emb + ((size_t)n*1024 + m)*128);
            const float* xr = &xsf[e*132];
            float cc = 0.f;
            #pragma unroll 8
            for (int qq = 0; qq < 32; qq++) {
                float4 e4 = er4[qq];
                cc = fmaf(xr[qq*4+0], e4.x, cc);
                cc = fmaf(xr[qq*4+1], e4.y, cc);
                cc = fmaf(xr[qq*4+2], e4.z, cc);
                cc = fmaf(xr[qq*4+3], e4.w, cc);
            }
            Dv[tid] = __fsub_rn(__fadd_rn(g_esq[n*1024 + m], g_xsq[n*LPER + l]), 2.f*cc);
        }
        __syncthreads();
        if (tid < nent) {
            int m0 = ent[tid].y & 0xffff, m1 = ent[tid].y >> 16;
            float D0 = Dv[2*tid], D1 = Dv[2*tid + 1];
            int win;
            if (D0 < D1) win = m0;
            else if (D1 < D0) win = m1;
            else win = (m0 < m1) ? m0 : m1;
            int nl = ent[tid].x;
            g_indices[(nl >> 14)*LPER + (nl & 16383)] = win;
        }
        __syncthreads();
    }
}

// ---------------- pass 2b: full exact rescan, E staged in smem ----------------
__global__ void __launch_bounds__(128)
rescan_kernel(const float* __restrict__ emb) {
    extern __shared__ float fsm[];
    float* E     = fsm;                       // [128 codes][stride 132]
    float* xs    = fsm + 128*132;             // [8 rows][128]
    float* esq_c = xs + 1024;                 // [128]
    float* xsq_s = esq_c + 128;               // [8]
    unsigned long long* wred = (unsigned long long*)(xsq_s + 8);   // [4][8]

    const int n     = blockIdx.x >> 7;
    const int mc    = (blockIdx.x >> 4) & 7;
    const int slice = blockIdx.x & 15;
    const int tid   = threadIdx.x;
    const int wid   = tid >> 5, lane = tid & 31;

    const int cnt = g_rcnt[n];
    if (cnt == 0) return;

    const float* src = emb + ((size_t)n*1024 + mc*128)*128;
    for (int i = tid; i < 16384; i += 128) {
        int r = i >> 7, d = i & 127;
        E[r*132 + d] = src[i];
    }
    esq_c[tid] = g_esq[n*1024 + mc*128 + tid];
    __syncthreads();

    const unsigned code_m = (unsigned)(mc*128 + tid);

    for (int g0 = slice*8; g0 < cnt; g0 += 16*8) {
        #pragma unroll
        for (int r = 0; r < 8; r++) {
            int u = g0 + r;
            int uc = (u < cnt) ? u : (cnt - 1);
            xs[r*128 + tid] = g_xpr[((size_t)n*LPER + uc)*128 + tid];
        }
        if (tid < 8) {
            int u = g0 + tid;
            int uc = (u < cnt) ? u : (cnt - 1);
            xsq_s[tid] = g_xsq[n*LPER + g_rlist[n*LPER + uc]];
        }
        __syncthreads();

        float c[8];
        #pragma unroll
        for (int r = 0; r < 8; r++) c[r] = 0.f;
        const float4* er4 = (const float4*)&E[tid*132];
        #pragma unroll 8
        for (int qq = 0; qq < 32; qq++) {
            float4 e = er4[qq];
            #pragma unroll
            for (int r = 0; r < 8; r++) {
                float4 xr = *(const float4*)&xs[r*128 + qq*4];
                c[r] = fmaf(xr.x, e.x, c[r]);
                c[r] = fmaf(xr.y, e.y, c[r]);
                c[r] = fmaf(xr.z, e.z, c[r]);
                c[r] = fmaf(xr.w, e.w, c[r]);
            }
        }

        #pragma unroll
        for (int r = 0; r < 8; r++) {
            float D = __fsub_rn(__fadd_rn(esq_c[tid], xsq_s[r]), 2.f*c[r]);
            unsigned ud = __float_as_uint(D);
            ud = (ud & 0x80000000u) ? ~ud : (ud | 0x80000000u);
            unsigned long long key = ((unsigned long long)ud << 32) | code_m;
            #pragma unroll
            for (int o = 16; o; o >>= 1) {
                unsigned long long ok = __shfl_xor_sync(0xffffffffu, key, o);
                if (ok < key) key = ok;
            }
            if (lane == 0) wred[wid*8 + r] = key;
        }
        __syncthreads();
        if (tid < 8) {
            int u = g0 + tid;
            if (u < cnt) {
                unsigned long long k = wred[tid];
                if (wred[8  + tid] < k) k = wred[8  + tid];
                if (wred[16 + tid] < k) k = wred[16 + tid];
                if (wred[24 + tid] < k) k = wred[24 + tid];
                int l = g_rlist[n*LPER + u];
                atomicMin(&g_fixkey[n*LPER + l], k);
            }
        }
        __syncthreads();
    }
}

// ---------------- unpack rescan indices ----------------
__global__ void unpack_kernel() {
    const int n = blockIdx.x;
    const int cnt = g_rcnt[n];
    for (int p = threadIdx.x; p < cnt; p += blockDim.x) {
        int l = g_rlist[n*LPER + p];
        int id = n*LPER + l;
        g_indices[id] = (int)(unsigned)(g_fixkey[id] & 0xFFFFFFFFull);
    }
}

// ---------------- gather + z_q + loss partials + indices out (float4) ----------------
__global__ void __launch_bounds__(256)
gather_kernel(const float* __restrict__ x, const float* __restrict__ emb,
              float* __restrict__ out, float* __restrict__ out_idx, int write_extras) {
    __shared__ int   midx[64];
    __shared__ float rows[64*129];
    __shared__ float red[256];
    const int n = blockIdx.x & 7, b = blockIdx.x >> 3, tid = threadIdx.x;

    if (tid < 64) {
        int m = g_indices[n*LPER + b*HLAT + tid];
        midx[tid] = m;
        if (write_extras) out_idx[b*(NCB*HLAT) + n*HLAT + tid] = (float)m;
    }
    __syncthreads();
    for (int idx = tid; idx < 64*32; idx += 256) {
        int r = idx >> 5, dq = (idx & 31) * 4;
        float4 v = *(const float4*)&emb[((size_t)n*MEMB + midx[r])*DEMB + dq];
        float* dst = &rows[r*129 + dq];
        dst[0] = v.x; dst[1] = v.y; dst[2] = v.z; dst[3] = v.w;
    }
    __syncthreads();
    float s = 0.f;
    const size_t base = (size_t)b*65536 + (size_t)n*8192;
    for (int idx4 = tid; idx4 < 2048; idx4 += 256) {
        int d = idx4 >> 4, h4 = (idx4 & 15) * 4;
        float4 q;
        q.x = rows[(h4+0)*129 + d];
        q.y = rows[(h4+1)*129 + d];
        q.z = rows[(h4+2)*129 + d];
        q.w = rows[(h4+3)*129 + d];
        float4 xv = *(const float4*)&x[base + d*64 + h4];
        *(float4*)&out[base + d*64 + h4] = q;
        float dx = xv.x - q.x, dy = xv.y - q.y, dz = xv.z - q.z, dw = xv.w - q.w;
        s += dx*dx + dy*dy + dz*dz + dw*dw;
    }
    red[tid] = s;
    __syncthreads();
    for (int st = 128; st; st >>= 1) { if (tid < st) red[tid] += red[tid+st]; __syncthreads(); }
    if (tid == 0) g_part[blockIdx.x] = red[0];
}

// ---------------- entropy ----------------
__global__ void entropy_kernel() {
    __shared__ int   hist[MEMB];
    __shared__ float red[256];
    const int n = blockIdx.x, tid = threadIdx.x;
    for (int i = tid; i < MEMB; i += 256) hist[i] = 0;
    __syncthreads();
    for (int l = tid; l < LPER; l += 256) atomicAdd(&hist[g_indices[n*LPER + l]], 1);
    __syncthreads();
    float s = 0.f;
    for (int m = tid; m < MEMB; m += 256) {
        float p = (float)hist[m] * (1.f / (float)LPER);
        s += p * logf(p + 1e-10f);
    }
    red[tid] = s;
    __syncthreads();
    for (int st = 128; st; st >>= 1) { if (tid < st) red[tid] += red[tid+st]; __syncthreads(); }
    if (tid == 0) g_ent[n] = -red[0];
}

// ---------------- finalize ----------------
__global__ void finalize_kernel(float* __restrict__ out, int write_scalars) {
    __shared__ float red[256];
    const int tid = threadIdx.x;
    float s = 0.f;
    for (int i = tid; i < 2048; i += 256) s += g_part[i];
    red[tid] = s;
    __syncthreads();
    for (int st = 128; st; st >>= 1) { if (tid < st) red[tid] += red[tid+st]; __syncthreads(); }
    if (tid == 0 && write_scalars) {
        float loss = 0.25f * red[0] / (float)ZQ_ELEMS;
        float ent = 0.f, perp = 0.f;
        #pragma unroll
        for (int n = 0; n < NCB; n++) { ent += g_ent[n]; perp += expf(g_ent[n]); }
        out[ZQ_ELEMS + 0] = loss;
        out[ZQ_ELEMS + 1] = ent * (1.f / NCB);
        out[ZQ_ELEMS + 2] = perp * (1.f / NCB);
    }
}

// ---------------- launch ----------------
extern "C" void kernel_launch(void* const* d_in, const int* in_sizes, int n_in,
                              void* d_out, int out_size) {
    const float* x   = (const float*)d_in[0];
    const float* emb = (const float*)d_in[1];
    if (n_in >= 2 && in_sizes[0] == NCB*MEMB*DEMB && in_sizes[1] == ZQ_ELEMS) {
        const float* t = x; x = emb; emb = t;
    }
    float* out = (float*)d_out;
    const int full = (out_size >= ZQ_ELEMS + 3 + IDX_ELEMS) ? 1 : 0;

    const int SMEM_ARG = 56320;
    cudaFuncSetAttribute(argmin_mma, cudaFuncAttributeMaxDynamicSharedMemorySize, SMEM_ARG);
    const int SMEM_PAIR = 128*132*4;
    cudaFuncSetAttribute(pairfix_kernel, cudaFuncAttributeMaxDynamicSharedMemorySize, SMEM_PAIR);
    const int SMEM_RES = (128*132 + 8*128 + 128 + 8) * 4 + 32 * 8;
    cudaFuncSetAttribute(rescan_kernel, cudaFuncAttributeMaxDynamicSharedMemorySize, SMEM_RES);

    esq_kernel<<<(NCB*MEMB + 255)/256, 256>>>(emb);
    xsq_kernel<<<BATCH*NCB, 256>>>(x);
    bprep_kernel<<<(NCB*MEMB*DEMB + 255)/256, 256>>>(emb);
    argmin_mma<<<NCB * (LPER/64), 256, SMEM_ARG>>>(x);
    packP_kernel<<<2048, 128>>>(x);
    packR_kernel<<<dim3(256, NCB), 128>>>(x);
    pairfix_kernel<<<296, 256, SMEM_PAIR>>>(emb);
    rescan_kernel<<<NCB*8*16, 128, SMEM_RES>>>(emb);
    unpack_kernel<<<NCB, 256>>>();
    gather_kernel<<<BATCH*NCB, 256>>>(x, emb, out, out + ZQ_ELEMS + 3, full);
    entropy_kernel<<<NCB, 256>>>();
    finalize_kernel<<<1, 256>>>(out, full);
}